// round 1
// baseline (speedup 1.0000x reference)
#include <cuda_runtime.h>
#include <cstdint>
#include <cstddef>

// Problem constants
#define BB   8
#define TT   2048
#define DD   512
#define HH   8
#define DHH  64
#define MTOT (BB*TT)   // 16384

// Scratch (device globals; no allocation allowed)
__device__ __align__(16) float g_Q [BB*HH*TT*DHH];
__device__ __align__(16) float g_KP[BB*HH*TT*DHH];
__device__ __align__(16) float g_V [BB*HH*TT*DHH];
__device__ __align__(16) float g_C [(size_t)MTOT*DD];

// ---------------------------------------------------------------------------
// TF32 helpers
// ---------------------------------------------------------------------------
__device__ __forceinline__ float tf32r(float x) {
    uint32_t u;
    asm("cvt.rna.tf32.f32 %0, %1;" : "=r"(u) : "f"(x));
    return __uint_as_float(u);
}

__device__ __forceinline__ void mma8(float* d, const uint32_t* a, uint32_t b0, uint32_t b1) {
    asm volatile(
        "mma.sync.aligned.m16n8k8.row.col.f32.tf32.tf32.f32 "
        "{%0,%1,%2,%3}, {%4,%5,%6,%7}, {%8,%9}, {%0,%1,%2,%3};\n"
        : "+f"(d[0]), "+f"(d[1]), "+f"(d[2]), "+f"(d[3])
        : "r"(a[0]), "r"(a[1]), "r"(a[2]), "r"(a[3]), "r"(b0), "r"(b1));
}

// ---------------------------------------------------------------------------
// Shared-memory tiled TF32 GEMM accumulator:
//   acc[2][8][4] += A[m0:m0+128, :512] * W[n0:n0+128, :512]^T   (out = A W^T)
// Block: 256 threads = 8 warps arranged 4(m) x 2(n); warp tile 32x64.
// ---------------------------------------------------------------------------
#define GBK  32
#define GLDA 36   // BK + 4 pad; fragment loads (4r+c)%32 conflict-free

__device__ void gemm_accum(const float* __restrict__ A, const float* __restrict__ W,
                           int m0, int n0, float acc[2][8][4],
                           float* As, float* Bs)
{
    const int tid  = threadIdx.x;
    const int lane = tid & 31, warp = tid >> 5;
    const int wm = warp >> 1, wn = warp & 1;
    const int lr = tid >> 3;          // 0..31 (staging row)
    const int lc = (tid & 7) * 4;     // 0..28 (staging col, float4)
    const int g  = lane >> 2, tg = lane & 3;

    for (int kc = 0; kc < DD; kc += GBK) {
        #pragma unroll
        for (int j = 0; j < 4; ++j) {
            int r = lr + j * 32;
            float4 va = *reinterpret_cast<const float4*>(A + (size_t)(m0 + r) * DD + kc + lc);
            float* da = As + r * GLDA + lc;
            da[0] = tf32r(va.x); da[1] = tf32r(va.y); da[2] = tf32r(va.z); da[3] = tf32r(va.w);
            float4 vb = *reinterpret_cast<const float4*>(W + (size_t)(n0 + r) * DD + kc + lc);
            float* db = Bs + r * GLDA + lc;
            db[0] = tf32r(vb.x); db[1] = tf32r(vb.y); db[2] = tf32r(vb.z); db[3] = tf32r(vb.w);
        }
        __syncthreads();
        #pragma unroll
        for (int kk = 0; kk < GBK; kk += 8) {
            uint32_t a[2][4];
            #pragma unroll
            for (int mi = 0; mi < 2; ++mi) {
                const float* ap = As + (wm * 32 + mi * 16 + g) * GLDA + kk + tg;
                a[mi][0] = __float_as_uint(ap[0]);
                a[mi][1] = __float_as_uint(ap[8 * GLDA]);
                a[mi][2] = __float_as_uint(ap[4]);
                a[mi][3] = __float_as_uint(ap[8 * GLDA + 4]);
            }
            #pragma unroll
            for (int ni = 0; ni < 8; ++ni) {
                const float* bp_ = Bs + (wn * 64 + ni * 8 + g) * GLDA + kk + tg;
                uint32_t b0 = __float_as_uint(bp_[0]);
                uint32_t b1 = __float_as_uint(bp_[4]);
                mma8(acc[0][ni], a[0], b0, b1);
                mma8(acc[1][ni], a[1], b0, b1);
            }
        }
        __syncthreads();
    }
}

// ---------------------------------------------------------------------------
// Kernel 1: projections. z=0 -> Q, z=1 -> KP (= xWk^T + posWp^T), z=2 -> V.
// Output stored head-major [B, H, T, 64].
// ---------------------------------------------------------------------------
__global__ void __launch_bounds__(256) proj_kernel(
    const float* __restrict__ x,  const float* __restrict__ pos,
    const float* __restrict__ Wq, const float* __restrict__ bq,
    const float* __restrict__ Wk, const float* __restrict__ bk,
    const float* __restrict__ Wv, const float* __restrict__ bv,
    const float* __restrict__ Wp, const float* __restrict__ bp)
{
    __shared__ float As[128 * GLDA];
    __shared__ float Bs[128 * GLDA];
    float acc[2][8][4];
    #pragma unroll
    for (int i = 0; i < 2; ++i)
        #pragma unroll
        for (int j = 0; j < 8; ++j)
            #pragma unroll
            for (int k = 0; k < 4; ++k) acc[i][j][k] = 0.f;

    const int n0 = blockIdx.x * 128;
    const int m0 = blockIdx.y * 128;
    const int z  = blockIdx.z;

    const float* bias1;
    const float* bias2 = nullptr;
    float* dst;
    if (z == 0)      { gemm_accum(x, Wq, m0, n0, acc, As, Bs); bias1 = bq; dst = g_Q; }
    else if (z == 1) { gemm_accum(x, Wk, m0, n0, acc, As, Bs);
                       gemm_accum(pos, Wp, m0, n0, acc, As, Bs);
                       bias1 = bk; bias2 = bp; dst = g_KP; }
    else             { gemm_accum(x, Wv, m0, n0, acc, As, Bs); bias1 = bv; dst = g_V; }

    const int lane = threadIdx.x & 31, warp = threadIdx.x >> 5;
    const int wm = warp >> 1, wn = warp & 1;
    const int g = lane >> 2, tg = lane & 3;
    #pragma unroll
    for (int mi = 0; mi < 2; ++mi) {
        #pragma unroll
        for (int ni = 0; ni < 8; ++ni) {
            int r = m0 + wm * 32 + mi * 16 + g;
            int c = n0 + wn * 64 + ni * 8 + tg * 2;
            #pragma unroll
            for (int e = 0; e < 4; ++e) {
                int m = r + ((e >= 2) ? 8 : 0);
                int n = c + (e & 1);
                float v = acc[mi][ni][e] + bias1[n] + (bias2 ? bias2[n] : 0.f);
                int b_ = m >> 11, t = m & 2047, h = n >> 6, d = n & 63;
                dst[(((size_t)(b_ * HH + h)) * TT + t) * DHH + d] = v;
            }
        }
    }
}

// ---------------------------------------------------------------------------
// Kernel 2: flash attention over KP. One block = one (b,h) x 128 query rows.
// Non-causal, full softmax over T=2048 keys, chunks of 64.
// ---------------------------------------------------------------------------
#define ALD 68   // stride pad: (4r + c) % 32 distinct -> conflict-free frags

__global__ void __launch_bounds__(256) attn_kernel()
{
    extern __shared__ float sm[];
    float* Qs  = sm;                    // [128][68]
    float* Ks  = Qs  + 128 * ALD;       // [64][68]   (key-major, K[key][dh])
    float* Vs  = Ks  +  64 * ALD;       // [64][68]   (TRANSPOSED: V[dh][key])
    float* Ss  = Vs  +  64 * ALD;       // [128][68]  (scores / probs staging)
    float* mst = Ss  + 128 * ALD;       // [128]
    float* lst = mst + 128;             // [128]
    float* rsc = lst + 128;             // [128]

    const int tid  = threadIdx.x;
    const int lane = tid & 31, warp = tid >> 5;
    const int wm = warp >> 1, wn = warp & 1;   // 4(m) x 2(n)
    const int g  = lane >> 2, tg = lane & 3;

    const int bh = blockIdx.y;                 // 0..63 = b*8+h
    const int q0 = blockIdx.x * 128;
    const size_t base = (size_t)bh * TT * DHH;

    // Stage Q (tf32-rounded)
    #pragma unroll
    for (int j = 0; j < 8; ++j) {
        int f = tid + j * 256;                 // float4 index, 0..2047
        int r = f >> 4, c4 = (f & 15) * 4;
        float4 v = *reinterpret_cast<const float4*>(g_Q + base + (size_t)(q0 + r) * DHH + c4);
        float4 w = make_float4(tf32r(v.x), tf32r(v.y), tf32r(v.z), tf32r(v.w));
        *reinterpret_cast<float4*>(Qs + r * ALD + c4) = w;
    }
    if (tid < 128) { mst[tid] = -1e30f; lst[tid] = 0.f; }

    float acco[2][4][4];
    #pragma unroll
    for (int i = 0; i < 2; ++i)
        #pragma unroll
        for (int j = 0; j < 4; ++j)
            #pragma unroll
            for (int k = 0; k < 4; ++k) acco[i][j][k] = 0.f;

    __syncthreads();

    for (int kb = 0; kb < TT; kb += 64) {
        // ---- stage K chunk (key-major) ----
        #pragma unroll
        for (int j = 0; j < 4; ++j) {
            int f = tid + j * 256;             // 0..1023 float4
            int r = f >> 4, c4 = (f & 15) * 4;
            float4 v = *reinterpret_cast<const float4*>(g_KP + base + (size_t)(kb + r) * DHH + c4);
            *reinterpret_cast<float4*>(Ks + r * ALD + c4) =
                make_float4(tf32r(v.x), tf32r(v.y), tf32r(v.z), tf32r(v.w));
        }
        // ---- stage V chunk transposed: Vs[dh][key] ----
        {
            int key = tid & 63, dq = tid >> 6;
            #pragma unroll
            for (int j = 0; j < 4; ++j) {
                int dh0 = dq * 16 + j * 4;
                float4 v = *reinterpret_cast<const float4*>(g_V + base + (size_t)(kb + key) * DHH + dh0);
                Vs[(dh0 + 0) * ALD + key] = tf32r(v.x);
                Vs[(dh0 + 1) * ALD + key] = tf32r(v.y);
                Vs[(dh0 + 2) * ALD + key] = tf32r(v.z);
                Vs[(dh0 + 3) * ALD + key] = tf32r(v.w);
            }
        }
        __syncthreads();

        // ---- S = Q KP^T (128x64), warp tile 32x32 ----
        float accs[2][4][4];
        #pragma unroll
        for (int i = 0; i < 2; ++i)
            #pragma unroll
            for (int j = 0; j < 4; ++j)
                #pragma unroll
                for (int k = 0; k < 4; ++k) accs[i][j][k] = 0.f;

        #pragma unroll
        for (int kk = 0; kk < 64; kk += 8) {
            uint32_t a[2][4];
            #pragma unroll
            for (int mi = 0; mi < 2; ++mi) {
                const float* ap = Qs + (wm * 32 + mi * 16 + g) * ALD + kk + tg;
                a[mi][0] = __float_as_uint(ap[0]);
                a[mi][1] = __float_as_uint(ap[8 * ALD]);
                a[mi][2] = __float_as_uint(ap[4]);
                a[mi][3] = __float_as_uint(ap[8 * ALD + 4]);
            }
            #pragma unroll
            for (int ni = 0; ni < 4; ++ni) {
                const float* bp_ = Ks + (wn * 32 + ni * 8 + g) * ALD + kk + tg;
                uint32_t b0 = __float_as_uint(bp_[0]);
                uint32_t b1 = __float_as_uint(bp_[4]);
                mma8(accs[0][ni], a[0], b0, b1);
                mma8(accs[1][ni], a[1], b0, b1);
            }
        }
        // scale by 1/sqrt(64) and stage to Ss
        #pragma unroll
        for (int mi = 0; mi < 2; ++mi) {
            #pragma unroll
            for (int ni = 0; ni < 4; ++ni) {
                int r = wm * 32 + mi * 16 + g;
                int c = wn * 32 + ni * 8 + tg * 2;
                Ss[r * ALD + c]           = accs[mi][ni][0] * 0.125f;
                Ss[r * ALD + c + 1]       = accs[mi][ni][1] * 0.125f;
                Ss[(r + 8) * ALD + c]     = accs[mi][ni][2] * 0.125f;
                Ss[(r + 8) * ALD + c + 1] = accs[mi][ni][3] * 0.125f;
            }
        }
        __syncthreads();

        // ---- online softmax: 2 threads per row, 32 cols each ----
        {
            int r = tid >> 1, half = tid & 1;
            float* row = Ss + r * ALD + half * 32;
            float mloc = -1e30f;
            #pragma unroll
            for (int j2 = 0; j2 < 32; ++j2) mloc = fmaxf(mloc, row[j2]);
            mloc = fmaxf(mloc, __shfl_xor_sync(0xffffffffu, mloc, 1));
            float mold = mst[r];
            float mnew = fmaxf(mold, mloc);
            float s = 0.f;
            #pragma unroll
            for (int j2 = 0; j2 < 32; ++j2) {
                float p = __expf(row[j2] - mnew);
                s += p;
                row[j2] = tf32r(p);
            }
            s += __shfl_xor_sync(0xffffffffu, s, 1);
            if (half == 0) {
                float sc = __expf(mold - mnew);
                rsc[r] = sc;
                lst[r] = lst[r] * sc + s;
                mst[r] = mnew;
            }
        }
        __syncthreads();

        // ---- rescale O accumulators by exp(m_old - m_new) per row ----
        #pragma unroll
        for (int mi = 0; mi < 2; ++mi) {
            float sA = rsc[wm * 32 + mi * 16 + g];
            float sB = rsc[wm * 32 + mi * 16 + g + 8];
            #pragma unroll
            for (int ni = 0; ni < 4; ++ni) {
                acco[mi][ni][0] *= sA;
                acco[mi][ni][1] *= sA;
                acco[mi][ni][2] *= sB;
                acco[mi][ni][3] *= sB;
            }
        }

        // ---- O += P V (contract over 64 keys) ----
        #pragma unroll
        for (int kk = 0; kk < 64; kk += 8) {
            uint32_t a[2][4];
            #pragma unroll
            for (int mi = 0; mi < 2; ++mi) {
                const float* ap = Ss + (wm * 32 + mi * 16 + g) * ALD + kk + tg;
                a[mi][0] = __float_as_uint(ap[0]);
                a[mi][1] = __float_as_uint(ap[8 * ALD]);
                a[mi][2] = __float_as_uint(ap[4]);
                a[mi][3] = __float_as_uint(ap[8 * ALD + 4]);
            }
            #pragma unroll
            for (int ni = 0; ni < 4; ++ni) {
                const float* bp_ = Vs + (wn * 32 + ni * 8 + g) * ALD + kk + tg;
                uint32_t b0 = __float_as_uint(bp_[0]);
                uint32_t b1 = __float_as_uint(bp_[4]);
                mma8(acco[0][ni], a[0], b0, b1);
                mma8(acco[1][ni], a[1], b0, b1);
            }
        }
        __syncthreads();
    }

    // ---- normalize and write ctx to [B, T, D] ----
    const int b_ = bh >> 3, h = bh & 7;
    #pragma unroll
    for (int mi = 0; mi < 2; ++mi) {
        int rA = wm * 32 + mi * 16 + g;
        float iA = 1.f / lst[rA];
        float iB = 1.f / lst[rA + 8];
        #pragma unroll
        for (int ni = 0; ni < 4; ++ni) {
            int c = h * 64 + wn * 32 + ni * 8 + tg * 2;
            size_t o0 = ((size_t)(b_ * TT + q0 + rA)) * DD + c;
            size_t o1 = ((size_t)(b_ * TT + q0 + rA + 8)) * DD + c;
            g_C[o0]     = acco[mi][ni][0] * iA;
            g_C[o0 + 1] = acco[mi][ni][1] * iA;
            g_C[o1]     = acco[mi][ni][2] * iB;
            g_C[o1 + 1] = acco[mi][ni][3] * iB;
        }
    }
}

// ---------------------------------------------------------------------------
// Kernel 3: out = ctx @ Wo^T + bo
// ---------------------------------------------------------------------------
__global__ void __launch_bounds__(256) out_kernel(
    const float* __restrict__ Wo, const float* __restrict__ bo,
    float* __restrict__ out)
{
    __shared__ float As[128 * GLDA];
    __shared__ float Bs[128 * GLDA];
    float acc[2][8][4];
    #pragma unroll
    for (int i = 0; i < 2; ++i)
        #pragma unroll
        for (int j = 0; j < 8; ++j)
            #pragma unroll
            for (int k = 0; k < 4; ++k) acc[i][j][k] = 0.f;

    const int n0 = blockIdx.x * 128;
    const int m0 = blockIdx.y * 128;

    gemm_accum(g_C, Wo, m0, n0, acc, As, Bs);

    const int lane = threadIdx.x & 31, warp = threadIdx.x >> 5;
    const int wm = warp >> 1, wn = warp & 1;
    const int g = lane >> 2, tg = lane & 3;
    #pragma unroll
    for (int mi = 0; mi < 2; ++mi) {
        #pragma unroll
        for (int ni = 0; ni < 8; ++ni) {
            int r = m0 + wm * 32 + mi * 16 + g;
            int c = n0 + wn * 64 + ni * 8 + tg * 2;
            #pragma unroll
            for (int e = 0; e < 4; ++e) {
                int m = r + ((e >= 2) ? 8 : 0);
                int n = c + (e & 1);
                out[(size_t)m * DD + n] = acc[mi][ni][e] + bo[n];
            }
        }
    }
}

// ---------------------------------------------------------------------------
// Launch
// ---------------------------------------------------------------------------
extern "C" void kernel_launch(void* const* d_in, const int* in_sizes, int n_in,
                              void* d_out, int out_size)
{
    (void)in_sizes; (void)n_in; (void)out_size;
    const float* x   = (const float*)d_in[0];
    const float* pos = (const float*)d_in[1];
    const float* Wq  = (const float*)d_in[2];
    const float* bq  = (const float*)d_in[3];
    const float* Wk  = (const float*)d_in[4];
    const float* bk  = (const float*)d_in[5];
    const float* Wv  = (const float*)d_in[6];
    const float* bv  = (const float*)d_in[7];
    const float* Wp  = (const float*)d_in[8];
    const float* bp  = (const float*)d_in[9];
    const float* Wo  = (const float*)d_in[10];
    const float* bo  = (const float*)d_in[11];
    float* out = (float*)d_out;

    const int smem = (128 * ALD + 64 * ALD + 64 * ALD + 128 * ALD + 3 * 128) * (int)sizeof(float);
    cudaFuncSetAttribute(attn_kernel, cudaFuncAttributeMaxDynamicSharedMemorySize, smem);

    proj_kernel<<<dim3(4, 128, 3), 256>>>(x, pos, Wq, bq, Wk, bk, Wv, bv, Wp, bp);
    attn_kernel<<<dim3(16, 64), 256, smem>>>();
    out_kernel<<<dim3(4, 128), 256>>>(Wo, bo, out);
}

// round 4
// speedup vs baseline: 1.1678x; 1.1678x over previous
#include <cuda_runtime.h>
#include <cstdint>
#include <cstddef>

#define BB   8
#define TT   2048
#define DD   512
#define HH   8
#define DHH  64
#define MTOT (BB*TT)

// Scratch (device globals; no allocation allowed)
__device__ __align__(16) float g_xc[(size_t)MTOT*DD];     // tf32-rounded x
__device__ __align__(16) float g_pc[(size_t)MTOT*DD];     // tf32-rounded pos
__device__ __align__(16) float g_Wc[5*DD*DD];             // tf32-rounded Wq,Wk,Wv,Wp,Wo
__device__ __align__(16) float g_Q [BB*HH*TT*DHH];        // [bh][t][dh]   (tf32)
__device__ __align__(16) float g_KP[BB*HH*TT*DHH];        // [bh][t][dh]   (tf32)
__device__ __align__(16) float g_Vt[BB*HH*DHH*TT];        // [bh][dh][t]   (tf32, transposed)
__device__ __align__(16) float g_C [(size_t)MTOT*DD];     // ctx (tf32)

// ---------------------------------------------------------------------------
// Helpers
// ---------------------------------------------------------------------------
__device__ __forceinline__ float tf32r(float x) {
    uint32_t u; asm("cvt.rna.tf32.f32 %0, %1;" : "=r"(u) : "f"(x));
    return __uint_as_float(u);
}
__device__ __forceinline__ void mma8(float* d, const uint32_t* a, uint32_t b0, uint32_t b1) {
    asm volatile(
        "mma.sync.aligned.m16n8k8.row.col.f32.tf32.tf32.f32 "
        "{%0,%1,%2,%3}, {%4,%5,%6,%7}, {%8,%9}, {%0,%1,%2,%3};\n"
        : "+f"(d[0]), "+f"(d[1]), "+f"(d[2]), "+f"(d[3])
        : "r"(a[0]), "r"(a[1]), "r"(a[2]), "r"(a[3]), "r"(b0), "r"(b1));
}
__device__ __forceinline__ uint32_t s2u(const void* p) {
    uint32_t a;
    asm("{ .reg .u64 t; cvta.to.shared.u64 t, %1; cvt.u32.u64 %0, t; }" : "=r"(a) : "l"(p));
    return a;
}
#define CP16(d, s)   asm volatile("cp.async.cg.shared.global [%0], [%1], 16;" :: "r"(d), "l"(s))
#define CP_COMMIT()  asm volatile("cp.async.commit_group;" ::: "memory")
#define CP_WAIT0()   asm volatile("cp.async.wait_group 0;" ::: "memory")
#define CP_WAIT1()   asm volatile("cp.async.wait_group 1;" ::: "memory")

// ---------------------------------------------------------------------------
// Kernel 0: tf32 rounding prep (elementwise)
// which: 0 -> g_xc, 1 -> g_pc, 2..6 -> g_Wc + (which-2)*DD*DD
// ---------------------------------------------------------------------------
__global__ void __launch_bounds__(256) cvt_kernel(const float4* __restrict__ src, int which, int n4)
{
    float4* dst;
    if (which == 0)      dst = (float4*)g_xc;
    else if (which == 1) dst = (float4*)g_pc;
    else                 dst = (float4*)(g_Wc + (size_t)(which - 2) * DD * DD);
    int i = blockIdx.x * blockDim.x + threadIdx.x;
    int stride = gridDim.x * blockDim.x;
    for (; i < n4; i += stride) {
        float4 v = src[i];
        dst[i] = make_float4(tf32r(v.x), tf32r(v.y), tf32r(v.z), tf32r(v.w));
    }
}

// ---------------------------------------------------------------------------
// Tiled TF32 mma GEMM with cp.async double buffering.
// Block 256 thr = 8 warps (4m x 2n); block tile 128x128; warp tile 32x64; BK=32.
// As/Bs row stride GLDA=36 floats (conflict-free fragment loads).
// ---------------------------------------------------------------------------
#define GBK  32
#define GLDA 36
#define ASZ  (128*GLDA*4)        // 18432 B per matrix
#define BUFSZ (2*ASZ)            // A+B per buffer: 36864 B

__device__ __forceinline__ void gstage(const float* __restrict__ A, const float* __restrict__ W,
                                       int m0, int n0, int kc, uint32_t sbase, int tid)
{
    const char* Ab = (const char*)(A + (size_t)m0 * DD + kc);
    const char* Wb = (const char*)(W + (size_t)n0 * DD + kc);
    #pragma unroll
    for (int j = 0; j < 4; ++j) {
        int c = tid + j * 256;               // 0..1023 float4 slots
        int row = c >> 3, c16 = c & 7;
        uint32_t d = sbase + (uint32_t)row * (GLDA * 4) + (uint32_t)c16 * 16;
        const char* srcA = Ab + (size_t)row * (DD * 4) + c16 * 16;
        const char* srcW = Wb + (size_t)row * (DD * 4) + c16 * 16;
        CP16(d, srcA);
        CP16(d + ASZ, srcW);
    }
}

__device__ __forceinline__ void gcompute(const float* As, const float* Bs, float acc[2][8][4],
                                         int wm, int wn, int g, int tg)
{
    #pragma unroll
    for (int kk = 0; kk < GBK; kk += 8) {
        uint32_t a[2][4];
        #pragma unroll
        for (int mi = 0; mi < 2; ++mi) {
            const float* ap = As + (wm * 32 + mi * 16 + g) * GLDA + kk + tg;
            a[mi][0] = __float_as_uint(ap[0]);
            a[mi][1] = __float_as_uint(ap[8 * GLDA]);
            a[mi][2] = __float_as_uint(ap[4]);
            a[mi][3] = __float_as_uint(ap[8 * GLDA + 4]);
        }
        #pragma unroll
        for (int ni = 0; ni < 8; ++ni) {
            const float* bp_ = Bs + (wn * 64 + ni * 8 + g) * GLDA + kk + tg;
            uint32_t b0 = __float_as_uint(bp_[0]);
            uint32_t b1 = __float_as_uint(bp_[4]);
            mma8(acc[0][ni], a[0], b0, b1);
            mma8(acc[1][ni], a[1], b0, b1);
        }
    }
}

// D(128x128) = sum over (A0*W0^T [, A1*W1^T]) with K=512 each.
__device__ void gemm_pipe(const float* A0, const float* W0,
                          const float* A1, const float* W1,
                          int m0, int n0, float acc[2][8][4],
                          char* dyn, int tid)
{
    const uint32_t s0 = s2u(dyn);
    const int T = A1 ? 32 : 16;
    const int lane = tid & 31, warp = tid >> 5;
    const int wm = warp >> 1, wn = warp & 1;
    const int g = lane >> 2, tg = lane & 3;

    gstage(A0, W0, m0, n0, 0, s0, tid);
    CP_COMMIT();
    for (int it = 0; it < T; ++it) {
        if (it + 1 < T) {
            int it2 = it + 1;
            const float* A = (it2 < 16) ? A0 : A1;
            const float* W = (it2 < 16) ? W0 : W1;
            gstage(A, W, m0, n0, (it2 & 15) * GBK, s0 + (uint32_t)(it2 & 1) * BUFSZ, tid);
            CP_COMMIT();
            CP_WAIT1();
        } else {
            CP_WAIT0();
        }
        __syncthreads();
        const float* As = (const float*)(dyn + (size_t)(it & 1) * BUFSZ);
        const float* Bs = (const float*)(dyn + (size_t)(it & 1) * BUFSZ + ASZ);
        gcompute(As, Bs, acc, wm, wn, g, tg);
        __syncthreads();
    }
}

// ---------------------------------------------------------------------------
// Kernel 1: projections. z=0 -> KP (2x work, scheduled first), z=1 -> Q, z=2 -> V.
// ---------------------------------------------------------------------------
__global__ void __launch_bounds__(256, 2) proj_mma(
    const float* __restrict__ bq, const float* __restrict__ bk,
    const float* __restrict__ bv, const float* __restrict__ bp)
{
    extern __shared__ char dyn[];
    float acc[2][8][4];
    #pragma unroll
    for (int i = 0; i < 2; ++i)
        #pragma unroll
        for (int j = 0; j < 8; ++j)
            #pragma unroll
            for (int k = 0; k < 4; ++k) acc[i][j][k] = 0.f;

    const int tid = threadIdx.x;
    const int n0 = blockIdx.x * 128;
    const int m0 = blockIdx.y * 128;
    const int z  = blockIdx.z;

    const float* Wq = g_Wc;
    const float* Wk = g_Wc + (size_t)1 * DD * DD;
    const float* Wv = g_Wc + (size_t)2 * DD * DD;
    const float* Wp = g_Wc + (size_t)3 * DD * DD;

    const float *b1, *b2 = nullptr;
    float* dst;
    if (z == 0)      { gemm_pipe(g_xc, Wk, g_pc, Wp, m0, n0, acc, dyn, tid); b1 = bk; b2 = bp; dst = g_KP; }
    else if (z == 1) { gemm_pipe(g_xc, Wq, nullptr, nullptr, m0, n0, acc, dyn, tid); b1 = bq; dst = g_Q; }
    else             { gemm_pipe(g_xc, Wv, nullptr, nullptr, m0, n0, acc, dyn, tid); b1 = bv; dst = nullptr; }

    const int lane = tid & 31, warp = tid >> 5;
    const int wm = warp >> 1, wn = warp & 1;
    const int g = lane >> 2, tg = lane & 3;
    #pragma unroll
    for (int mi = 0; mi < 2; ++mi) {
        #pragma unroll
        for (int ni = 0; ni < 8; ++ni) {
            int r = m0 + wm * 32 + mi * 16 + g;
            int c = n0 + wn * 64 + ni * 8 + tg * 2;
            #pragma unroll
            for (int e = 0; e < 4; ++e) {
                int m = r + ((e >= 2) ? 8 : 0);
                int n = c + (e & 1);
                float v = tf32r(acc[mi][ni][e] + b1[n] + (b2 ? b2[n] : 0.f));
                int b_ = m >> 11, t = m & 2047, h = n >> 6, d = n & 63;
                if (z == 2)
                    g_Vt[((size_t)(b_ * HH + h) * DHH + d) * TT + t] = v;
                else
                    dst[((size_t)(b_ * HH + h) * TT + t) * DHH + d] = v;
            }
        }
    }
}

// ---------------------------------------------------------------------------
// Kernel 2: flash attention (mma.sync). Block = (b,h) x 128 q-rows, 256 thr.
// 32 chunks of 64 keys, cp.async double-buffered K/V.
// ---------------------------------------------------------------------------
#define ALD 68

__device__ __forceinline__ void stage_kv(int bh, int kb, uint32_t ks, uint32_t vs, int tid)
{
    const char* Ksrc = (const char*)g_KP + ((size_t)bh * TT + kb) * (DHH * 4);
    const char* Vsrc = (const char*)g_Vt + ((size_t)bh * DHH * TT + kb) * 4;
    #pragma unroll
    for (int j = 0; j < 4; ++j) {
        int c = tid + j * 256;               // 0..1023: 64 rows x 16 float4
        int row = c >> 4, c16 = c & 15;
        CP16(ks + (uint32_t)row * (ALD * 4) + (uint32_t)c16 * 16,
             Ksrc + (size_t)row * 256 + c16 * 16);
    }
    #pragma unroll
    for (int j = 0; j < 4; ++j) {
        int c = tid + j * 256;               // 64 dh-rows x 16 float4 (keys contiguous)
        int dh = c >> 4, c16 = c & 15;
        CP16(vs + (uint32_t)dh * (ALD * 4) + (uint32_t)c16 * 16,
             Vsrc + (size_t)dh * (TT * 4) + c16 * 16);
    }
}

__global__ void __launch_bounds__(256) attn_mma()
{
    extern __shared__ char dyn[];
    float* Qs  = (float*)dyn;                 // [128][68]
    float* Ks0 = Qs  + 128 * ALD;             // [64][68] x2
    float* Vs0 = Ks0 + 2 * 64 * ALD;          // [64][68] x2   (V[dh][key])
    float* Ss  = Vs0 + 2 * 64 * ALD;          // [128][68]
    float* mst = Ss  + 128 * ALD;
    float* lst = mst + 128;
    float* rsc = lst + 128;

    const int tid  = threadIdx.x;
    const int lane = tid & 31, warp = tid >> 5;
    const int wm = warp >> 1, wn = warp & 1;
    const int g  = lane >> 2, tg = lane & 3;

    const int bh = blockIdx.y;
    const int q0 = blockIdx.x * 128;
    const size_t base = (size_t)bh * TT * DHH;

    // stage Q (already tf32) + chunk 0
    {
        const char* Qsrc = (const char*)g_Q + (base + (size_t)q0 * DHH) * 4;
        uint32_t qs = s2u(Qs);
        #pragma unroll
        for (int j = 0; j < 8; ++j) {
            int c = tid + j * 256;            // 128 rows x 16 float4
            int row = c >> 4, c16 = c & 15;
            CP16(qs + (uint32_t)row * (ALD * 4) + (uint32_t)c16 * 16,
                 Qsrc + (size_t)row * 256 + c16 * 16);
        }
    }
    stage_kv(bh, 0, s2u(Ks0), s2u(Vs0), tid);
    CP_COMMIT();

    if (tid < 128) { mst[tid] = -1e30f; lst[tid] = 0.f; }

    float acco[2][4][4];
    #pragma unroll
    for (int i = 0; i < 2; ++i)
        #pragma unroll
        for (int j = 0; j < 4; ++j)
            #pragma unroll
            for (int k = 0; k < 4; ++k) acco[i][j][k] = 0.f;

    for (int cb = 0; cb < 32; ++cb) {
        const int buf = cb & 1;
        const float* Ks = Ks0 + buf * 64 * ALD;
        const float* Vs = Vs0 + buf * 64 * ALD;

        if (cb + 1 < 32) {
            stage_kv(bh, (cb + 1) * 64,
                     s2u(Ks0 + (buf ^ 1) * 64 * ALD),
                     s2u(Vs0 + (buf ^ 1) * 64 * ALD), tid);
            CP_COMMIT();
            CP_WAIT1();
        } else {
            CP_WAIT0();
        }
        __syncthreads();

        // ---- S = Q KP^T (128x64), warp tile 32x32 ----
        float accs[2][4][4];
        #pragma unroll
        for (int i = 0; i < 2; ++i)
            #pragma unroll
            for (int j = 0; j < 4; ++j)
                #pragma unroll
                for (int k = 0; k < 4; ++k) accs[i][j][k] = 0.f;

        #pragma unroll
        for (int kk = 0; kk < 64; kk += 8) {
            uint32_t a[2][4];
            #pragma unroll
            for (int mi = 0; mi < 2; ++mi) {
                const float* ap = Qs + (wm * 32 + mi * 16 + g) * ALD + kk + tg;
                a[mi][0] = __float_as_uint(ap[0]);
                a[mi][1] = __float_as_uint(ap[8 * ALD]);
                a[mi][2] = __float_as_uint(ap[4]);
                a[mi][3] = __float_as_uint(ap[8 * ALD + 4]);
            }
            #pragma unroll
            for (int ni = 0; ni < 4; ++ni) {
                const float* bp_ = Ks + (wn * 32 + ni * 8 + g) * ALD + kk + tg;
                uint32_t b0 = __float_as_uint(bp_[0]);
                uint32_t b1 = __float_as_uint(bp_[4]);
                mma8(accs[0][ni], a[0], b0, b1);
                mma8(accs[1][ni], a[1], b0, b1);
            }
        }
        #pragma unroll
        for (int mi = 0; mi < 2; ++mi) {
            #pragma unroll
            for (int ni = 0; ni < 4; ++ni) {
                int r = wm * 32 + mi * 16 + g;
                int c = wn * 32 + ni * 8 + tg * 2;
                Ss[r * ALD + c]           = accs[mi][ni][0] * 0.125f;
                Ss[r * ALD + c + 1]       = accs[mi][ni][1] * 0.125f;
                Ss[(r + 8) * ALD + c]     = accs[mi][ni][2] * 0.125f;
                Ss[(r + 8) * ALD + c + 1] = accs[mi][ni][3] * 0.125f;
            }
        }
        __syncthreads();

        // ---- online softmax: 2 threads per row ----
        {
            int r = tid >> 1, half = tid & 1;
            float* row = Ss + r * ALD + half * 32;
            float mloc = -1e30f;
            #pragma unroll
            for (int j2 = 0; j2 < 32; ++j2) mloc = fmaxf(mloc, row[j2]);
            mloc = fmaxf(mloc, __shfl_xor_sync(0xffffffffu, mloc, 1));
            float mold = mst[r];
            float mnew = fmaxf(mold, mloc);
            float s = 0.f;
            #pragma unroll
            for (int j2 = 0; j2 < 32; ++j2) {
                float p = __expf(row[j2] - mnew);
                s += p;
                row[j2] = tf32r(p);
            }
            s += __shfl_xor_sync(0xffffffffu, s, 1);
            if (half == 0) {
                float sc = __expf(mold - mnew);
                rsc[r] = sc;
                lst[r] = lst[r] * sc + s;
                mst[r] = mnew;
            }
        }
        __syncthreads();

        // ---- rescale O, then O += P V ----
        #pragma unroll
        for (int mi = 0; mi < 2; ++mi) {
            float sA = rsc[wm * 32 + mi * 16 + g];
            float sB = rsc[wm * 32 + mi * 16 + g + 8];
            #pragma unroll
            for (int ni = 0; ni < 4; ++ni) {
                acco[mi][ni][0] *= sA;
                acco[mi][ni][1] *= sA;
                acco[mi][ni][2] *= sB;
                acco[mi][ni][3] *= sB;
            }
        }
        #pragma unroll
        for (int kk = 0; kk < 64; kk += 8) {
            uint32_t a[2][4];
            #pragma unroll
            for (int mi = 0; mi < 2; ++mi) {
                const float* ap = Ss + (wm * 32 + mi * 16 + g) * ALD + kk + tg;
                a[mi][0] = __float_as_uint(ap[0]);
                a[mi][1] = __float_as_uint(ap[8 * ALD]);
                a[mi][2] = __float_as_uint(ap[4]);
                a[mi][3] = __float_as_uint(ap[8 * ALD + 4]);
            }
            #pragma unroll
            for (int ni = 0; ni < 4; ++ni) {
                const float* bp_ = Vs + (wn * 32 + ni * 8 + g) * ALD + kk + tg;
                uint32_t b0 = __float_as_uint(bp_[0]);
                uint32_t b1 = __float_as_uint(bp_[4]);
                mma8(acco[0][ni], a[0], b0, b1);
                mma8(acco[1][ni], a[1], b0, b1);
            }
        }
        __syncthreads();
    }

    // ---- normalize, write ctx (tf32-rounded for the out GEMM) ----
    const int b_ = bh >> 3, h = bh & 7;
    #pragma unroll
    for (int mi = 0; mi < 2; ++mi) {
        int rA = wm * 32 + mi * 16 + g;
        float iA = 1.f / lst[rA];
        float iB = 1.f / lst[rA + 8];
        #pragma unroll
        for (int ni = 0; ni < 4; ++ni) {
            int c = h * 64 + wn * 32 + ni * 8 + tg * 2;
            size_t o0 = ((size_t)(b_ * TT + q0 + rA)) * DD + c;
            size_t o1 = ((size_t)(b_ * TT + q0 + rA + 8)) * DD + c;
            g_C[o0]     = tf32r(acco[mi][ni][0] * iA);
            g_C[o0 + 1] = tf32r(acco[mi][ni][1] * iA);
            g_C[o1]     = tf32r(acco[mi][ni][2] * iB);
            g_C[o1 + 1] = tf32r(acco[mi][ni][3] * iB);
        }
    }
}

// ---------------------------------------------------------------------------
// Kernel 3: out = ctx @ Wo^T + bo
// ---------------------------------------------------------------------------
__global__ void __launch_bounds__(256, 2) out_mma(const float* __restrict__ bo,
                                                 float* __restrict__ out)
{
    extern __shared__ char dyn[];
    float acc[2][8][4];
    #pragma unroll
    for (int i = 0; i < 2; ++i)
        #pragma unroll
        for (int j = 0; j < 8; ++j)
            #pragma unroll
            for (int k = 0; k < 4; ++k) acc[i][j][k] = 0.f;

    const int tid = threadIdx.x;
    const int n0 = blockIdx.x * 128;
    const int m0 = blockIdx.y * 128;
    const float* Wo = g_Wc + (size_t)4 * DD * DD;

    gemm_pipe(g_C, Wo, nullptr, nullptr, m0, n0, acc, dyn, tid);

    const int lane = tid & 31, warp = tid >> 5;
    const int wm = warp >> 1, wn = warp & 1;
    const int g = lane >> 2, tg = lane & 3;
    #pragma unroll
    for (int mi = 0; mi < 2; ++mi) {
        #pragma unroll
        for (int ni = 0; ni < 8; ++ni) {
            int r = m0 + wm * 32 + mi * 16 + g;
            int c = n0 + wn * 64 + ni * 8 + tg * 2;
            #pragma unroll
            for (int e = 0; e < 4; ++e) {
                int m = r + ((e >= 2) ? 8 : 0);
                int n = c + (e & 1);
                out[(size_t)m * DD + n] = acc[mi][ni][e] + bo[n];
            }
        }
    }
}

// ---------------------------------------------------------------------------
// Launch
// ---------------------------------------------------------------------------
extern "C" void kernel_launch(void* const* d_in, const int* in_sizes, int n_in,
                              void* d_out, int out_size)
{
    (void)in_sizes; (void)n_in; (void)out_size;
    const float* x   = (const float*)d_in[0];
    const float* pos = (const float*)d_in[1];
    const float* Wq  = (const float*)d_in[2];
    const float* bq  = (const float*)d_in[3];
    const float* Wk  = (const float*)d_in[4];
    const float* bk  = (const float*)d_in[5];
    const float* Wv  = (const float*)d_in[6];
    const float* bv  = (const float*)d_in[7];
    const float* Wp  = (const float*)d_in[8];
    const float* bp  = (const float*)d_in[9];
    const float* Wo  = (const float*)d_in[10];
    const float* bo  = (const float*)d_in[11];
    float* out = (float*)d_out;

    const int n4x = MTOT * DD / 4;      // 2097152
    const int n4w = DD * DD / 4;        // 65536

    cvt_kernel<<<2048, 256>>>((const float4*)x,   0, n4x);
    cvt_kernel<<<2048, 256>>>((const float4*)pos, 1, n4x);
    cvt_kernel<<<256, 256>>>((const float4*)Wq, 2, n4w);
    cvt_kernel<<<256, 256>>>((const float4*)Wk, 3, n4w);
    cvt_kernel<<<256, 256>>>((const float4*)Wv, 4, n4w);
    cvt_kernel<<<256, 256>>>((const float4*)Wp, 5, n4w);
    cvt_kernel<<<256, 256>>>((const float4*)Wo, 6, n4w);

    const int smem_g = 2 * BUFSZ;                                    // 73728
    const int smem_a = (128 * ALD + 2 * 64 * ALD + 2 * 64 * ALD
                        + 128 * ALD + 3 * 128) * (int)sizeof(float); // ~140KB
    cudaFuncSetAttribute(proj_mma, cudaFuncAttributeMaxDynamicSharedMemorySize, smem_g);
    cudaFuncSetAttribute(attn_mma, cudaFuncAttributeMaxDynamicSharedMemorySize, smem_a);
    cudaFuncSetAttribute(out_mma,  cudaFuncAttributeMaxDynamicSharedMemorySize, smem_g);

    proj_mma<<<dim3(4, 128, 3), 256, smem_g>>>(bq, bk, bv, bp);
    attn_mma<<<dim3(16, 64), 256, smem_a>>>();
    out_mma<<<dim3(4, 128), 256, smem_g>>>(bo, out);
}

// round 6
// speedup vs baseline: 1.5958x; 1.3666x over previous
#include <cuda_runtime.h>
#include <cstdint>
#include <cstddef>

#define BB   8
#define TT   2048
#define DD   512
#define HH   8
#define DHH  64
#define MTOT (BB*TT)

// Scratch (device globals; no allocation allowed)
__device__ __align__(16) float g_xc[(size_t)MTOT*DD];     // tf32, k-paired
__device__ __align__(16) float g_pc[(size_t)MTOT*DD];     // tf32, k-paired
__device__ __align__(16) float g_Wc[5*DD*DD];             // tf32, k-paired (Wq,Wk,Wv,Wp,Wo)
__device__ __align__(16) float g_Q [BB*HH*TT*DHH];        // [bh][t][dh-paired]
__device__ __align__(16) float g_KP[BB*HH*TT*DHH];        // [bh][t][dh-paired]
__device__ __align__(16) float g_Vt[BB*HH*DHH*TT];        // [bh][dh][t-paired]
__device__ __align__(16) float g_C [(size_t)MTOT*DD];     // ctx, k-paired

// ---------------------------------------------------------------------------
// Helpers
// ---------------------------------------------------------------------------
__device__ __forceinline__ float tf32r(float x) {
    uint32_t u; asm("cvt.rna.tf32.f32 %0, %1;" : "=r"(u) : "f"(x));
    return __uint_as_float(u);
}
__device__ __forceinline__ uint32_t tf32b(float x) {
    uint32_t u; asm("cvt.rna.tf32.f32 %0, %1;" : "=r"(u) : "f"(x));
    return u;
}
__device__ __forceinline__ void mma8(float* d, const uint32_t* a, uint32_t b0, uint32_t b1) {
    asm volatile(
        "mma.sync.aligned.m16n8k8.row.col.f32.tf32.tf32.f32 "
        "{%0,%1,%2,%3}, {%4,%5,%6,%7}, {%8,%9}, {%0,%1,%2,%3};\n"
        : "+f"(d[0]), "+f"(d[1]), "+f"(d[2]), "+f"(d[3])
        : "r"(a[0]), "r"(a[1]), "r"(a[2]), "r"(a[3]), "r"(b0), "r"(b1));
}
__device__ __forceinline__ uint32_t s2u(const void* p) {
    uint32_t a;
    asm("{ .reg .u64 t; cvta.to.shared.u64 t, %1; cvt.u32.u64 %0, t; }" : "=r"(a) : "l"(p));
    return a;
}
// pair-permutation within 8-groups: k -> (k&3)*2 + (k>>2)
__device__ __forceinline__ int perm8(int c) {
    return (c & ~7) | ((c & 3) * 2 + ((c >> 2) & 1));
}
#define CP16(d, s)   asm volatile("cp.async.cg.shared.global [%0], [%1], 16;" :: "r"(d), "l"(s))
#define CP_COMMIT()  asm volatile("cp.async.commit_group;" ::: "memory")
#define CP_WAIT0()   asm volatile("cp.async.wait_group 0;" ::: "memory")
#define CP_WAIT1()   asm volatile("cp.async.wait_group 1;" ::: "memory")

// ---------------------------------------------------------------------------
// Kernel 0: tf32 rounding + k-pair permutation (elementwise over rows of 512)
// which: 0 -> g_xc, 1 -> g_pc, 2..6 -> g_Wc + (which-2)*DD*DD
// ---------------------------------------------------------------------------
__global__ void __launch_bounds__(256) cvt_kernel(const float4* __restrict__ src, int which, int n4)
{
    float* dst;
    if (which == 0)      dst = g_xc;
    else if (which == 1) dst = g_pc;
    else                 dst = g_Wc + (size_t)(which - 2) * DD * DD;
    int i = blockIdx.x * blockDim.x + threadIdx.x;
    int stride = gridDim.x * blockDim.x;
    const int q = DD / 4;
    for (; i < n4; i += stride) {
        float4 v = src[i];
        int row = i / q, c0 = (i - row * q) * 4;
        float* drow = dst + (size_t)row * DD;
        drow[perm8(c0 + 0)] = tf32r(v.x);
        drow[perm8(c0 + 1)] = tf32r(v.y);
        drow[perm8(c0 + 2)] = tf32r(v.z);
        drow[perm8(c0 + 3)] = tf32r(v.w);
    }
}

// ---------------------------------------------------------------------------
// Tiled TF32 mma GEMM with cp.async double buffering (paired-k layout).
// Block 256 thr = 8 warps (4m x 2n); block tile 128x128; warp tile 32x64; BK=32.
// ---------------------------------------------------------------------------
#define GBK  32
#define GLDA 40                  // 32 + 8 pad; 8B stride 20 == 4 mod 16 -> conflict-free
#define ASZ  (128*GLDA*4)        // 20480 B per matrix
#define BUFSZ (2*ASZ)            // 40960 B per buffer

__device__ __forceinline__ void gstage(const float* __restrict__ A, const float* __restrict__ W,
                                       int m0, int n0, int kc, uint32_t sbase, int tid)
{
    const char* Ab = (const char*)(A + (size_t)m0 * DD + kc);
    const char* Wb = (const char*)(W + (size_t)n0 * DD + kc);
    #pragma unroll
    for (int j = 0; j < 4; ++j) {
        int c = tid + j * 256;               // 0..1023 float4 slots (128 rows x 8)
        int row = c >> 3, c16 = c & 7;
        uint32_t d = sbase + (uint32_t)row * (GLDA * 4) + (uint32_t)c16 * 16;
        CP16(d,       Ab + (size_t)row * (DD * 4) + c16 * 16);
        CP16(d + ASZ, Wb + (size_t)row * (DD * 4) + c16 * 16);
    }
}

__device__ __forceinline__ void gcompute(const float* As, const float* Bs, float acc[2][8][4],
                                         int wm, int wn, int g, int tg)
{
    #pragma unroll
    for (int kk = 0; kk < GBK; kk += 8) {
        uint32_t a[2][4];
        #pragma unroll
        for (int mi = 0; mi < 2; ++mi) {
            float2 f0 = *(const float2*)(As + (wm * 32 + mi * 16 + g) * GLDA + kk + 2 * tg);
            float2 f1 = *(const float2*)(As + (wm * 32 + mi * 16 + g + 8) * GLDA + kk + 2 * tg);
            a[mi][0] = __float_as_uint(f0.x);
            a[mi][1] = __float_as_uint(f1.x);
            a[mi][2] = __float_as_uint(f0.y);
            a[mi][3] = __float_as_uint(f1.y);
        }
        #pragma unroll
        for (int ni = 0; ni < 8; ++ni) {
            float2 fb = *(const float2*)(Bs + (wn * 64 + ni * 8 + g) * GLDA + kk + 2 * tg);
            uint32_t b0 = __float_as_uint(fb.x);
            uint32_t b1 = __float_as_uint(fb.y);
            mma8(acc[0][ni], a[0], b0, b1);
            mma8(acc[1][ni], a[1], b0, b1);
        }
    }
}

__device__ void gemm_pipe(const float* A0, const float* W0,
                          const float* A1, const float* W1,
                          int m0, int n0, float acc[2][8][4],
                          char* dyn, int tid)
{
    const uint32_t s0 = s2u(dyn);
    const int T = A1 ? 32 : 16;
    const int lane = tid & 31, warp = tid >> 5;
    const int wm = warp >> 1, wn = warp & 1;
    const int g = lane >> 2, tg = lane & 3;

    gstage(A0, W0, m0, n0, 0, s0, tid);
    CP_COMMIT();
    for (int it = 0; it < T; ++it) {
        if (it + 1 < T) {
            int it2 = it + 1;
            const float* A = (it2 < 16) ? A0 : A1;
            const float* W = (it2 < 16) ? W0 : W1;
            gstage(A, W, m0, n0, (it2 & 15) * GBK, s0 + (uint32_t)(it2 & 1) * BUFSZ, tid);
            CP_COMMIT();
            CP_WAIT1();
        } else {
            CP_WAIT0();
        }
        __syncthreads();
        const float* As = (const float*)(dyn + (size_t)(it & 1) * BUFSZ);
        const float* Bs = (const float*)(dyn + (size_t)(it & 1) * BUFSZ + ASZ);
        gcompute(As, Bs, acc, wm, wn, g, tg);
        __syncthreads();
    }
}

// ---------------------------------------------------------------------------
// Kernel 1: projections. z=0 -> KP (2x work), z=1 -> Q, z=2 -> V (transposed out).
// Outputs stored with paired permutation on the *future contraction dim*:
//   Q/KP: dh paired; Vt: key(t) paired.
// ---------------------------------------------------------------------------
__global__ void __launch_bounds__(256, 2) proj_mma(
    const float* __restrict__ bq, const float* __restrict__ bk,
    const float* __restrict__ bv, const float* __restrict__ bp)
{
    extern __shared__ char dyn[];
    float acc[2][8][4];
    #pragma unroll
    for (int i = 0; i < 2; ++i)
        #pragma unroll
        for (int j = 0; j < 8; ++j)
            #pragma unroll
            for (int k = 0; k < 4; ++k) acc[i][j][k] = 0.f;

    const int tid = threadIdx.x;
    const int n0 = blockIdx.x * 128;
    const int m0 = blockIdx.y * 128;
    const int z  = blockIdx.z;

    const float* Wq = g_Wc;
    const float* Wk = g_Wc + (size_t)1 * DD * DD;
    const float* Wv = g_Wc + (size_t)2 * DD * DD;
    const float* Wp = g_Wc + (size_t)3 * DD * DD;

    const float *b1, *b2 = nullptr;
    if (z == 0)      { gemm_pipe(g_xc, Wk, g_pc, Wp, m0, n0, acc, dyn, tid); b1 = bk; b2 = bp; }
    else if (z == 1) { gemm_pipe(g_xc, Wq, nullptr, nullptr, m0, n0, acc, dyn, tid); b1 = bq; }
    else             { gemm_pipe(g_xc, Wv, nullptr, nullptr, m0, n0, acc, dyn, tid); b1 = bv; }

    const int lane = tid & 31, warp = tid >> 5;
    const int wm = warp >> 1, wn = warp & 1;
    const int g = lane >> 2, tg = lane & 3;
    #pragma unroll
    for (int mi = 0; mi < 2; ++mi) {
        #pragma unroll
        for (int ni = 0; ni < 8; ++ni) {
            int r = m0 + wm * 32 + mi * 16 + g;
            int c = n0 + wn * 64 + ni * 8 + tg * 2;
            #pragma unroll
            for (int e = 0; e < 4; ++e) {
                int m = r + ((e >= 2) ? 8 : 0);
                int n = c + (e & 1);
                float v = tf32r(acc[mi][ni][e] + b1[n] + (b2 ? b2[n] : 0.f));
                int b_ = m >> 11, t = m & 2047, h = n >> 6, d = n & 63;
                if (z == 2) {
                    g_Vt[((size_t)(b_ * HH + h) * DHH + d) * TT + perm8(t)] = v;
                } else {
                    float* dst = (z == 1) ? g_Q : g_KP;
                    dst[((size_t)(b_ * HH + h) * TT + t) * DHH + perm8(d)] = v;
                }
            }
        }
    }
}

// ---------------------------------------------------------------------------
// Kernel 2: register-resident flash attention.
// Block = (b,h) x 128 q-rows, 128 threads = 4 warps x 32 rows (full 64-key width).
// Q fragments in registers; softmax in registers (shfl over tg group);
// P C-frag -> A-frag via shuffles; 64-key chunks, cp.async double buffer.
// ---------------------------------------------------------------------------
#define ALD 72   // 64 + 8 pad; 8B stride 36 == 4 mod 16 -> conflict-free LDS.64
#define QSZ (128*ALD*4)
#define KSZ (64*ALD*4)

__device__ __forceinline__ void stage_kv(int bh, int kb, uint32_t ks, uint32_t vs, int tid)
{
    const char* Ksrc = (const char*)g_KP + ((size_t)bh * TT + kb) * (DHH * 4);
    const char* Vsrc = (const char*)g_Vt + ((size_t)bh * DHH * TT + kb) * 4;
    #pragma unroll
    for (int j = 0; j < 8; ++j) {
        int c = tid + j * 128;               // 0..1023: 64 rows x 16 float4
        int row = c >> 4, c16 = c & 15;
        CP16(ks + (uint32_t)row * (ALD * 4) + (uint32_t)c16 * 16,
             Ksrc + (size_t)row * 256 + c16 * 16);
        CP16(vs + (uint32_t)row * (ALD * 4) + (uint32_t)c16 * 16,
             Vsrc + (size_t)row * (TT * 4) + c16 * 16);
    }
}

__global__ void __launch_bounds__(128) attn_mma()
{
    extern __shared__ char dyn[];
    float* Qs = (float*)dyn;                      // [128][72]
    const uint32_t s0 = s2u(dyn);

    const int tid  = threadIdx.x;
    const int lane = tid & 31, wm = tid >> 5;     // 4 warps, 32 rows each
    const int g    = lane >> 2, tg = lane & 3;

    const int bh = blockIdx.y;
    const int q0 = blockIdx.x * 128;

    // stage Q + chunk 0 K/V
    {
        const char* Qsrc = (const char*)g_Q + ((size_t)bh * TT + q0) * (DHH * 4);
        #pragma unroll
        for (int j = 0; j < 16; ++j) {
            int c = tid + j * 128;                // 128 rows x 16 float4
            int row = c >> 4, c16 = c & 15;
            CP16(s0 + (uint32_t)row * (ALD * 4) + (uint32_t)c16 * 16,
                 Qsrc + (size_t)row * 256 + c16 * 16);
        }
    }
    stage_kv(bh, 0, s0 + QSZ, s0 + QSZ + 2 * KSZ, tid);
    CP_COMMIT();
    CP_WAIT0();
    __syncthreads();

    // Q fragments -> registers (once)
    uint32_t qf[2][8][4];
    #pragma unroll
    for (int mi = 0; mi < 2; ++mi)
        #pragma unroll
        for (int j = 0; j < 8; ++j) {
            float2 f0 = *(const float2*)(Qs + (wm * 32 + mi * 16 + g) * ALD + j * 8 + 2 * tg);
            float2 f1 = *(const float2*)(Qs + (wm * 32 + mi * 16 + g + 8) * ALD + j * 8 + 2 * tg);
            qf[mi][j][0] = __float_as_uint(f0.x);
            qf[mi][j][1] = __float_as_uint(f1.x);
            qf[mi][j][2] = __float_as_uint(f0.y);
            qf[mi][j][3] = __float_as_uint(f1.y);
        }

    float acco[2][8][4];
    #pragma unroll
    for (int i = 0; i < 2; ++i)
        #pragma unroll
        for (int j = 0; j < 8; ++j)
            #pragma unroll
            for (int k = 0; k < 4; ++k) acco[i][j][k] = 0.f;
    float mr0[2] = {-1e30f, -1e30f}, mr1[2] = {-1e30f, -1e30f};
    float lr0[2] = {0.f, 0.f},       lr1[2] = {0.f, 0.f};

    for (int cb = 0; cb < 32; ++cb) {
        const int buf = cb & 1;
        if (cb + 1 < 32) {
            stage_kv(bh, (cb + 1) * 64,
                     s0 + QSZ + (uint32_t)(buf ^ 1) * KSZ,
                     s0 + QSZ + 2 * KSZ + (uint32_t)(buf ^ 1) * KSZ, tid);
            CP_COMMIT();
            CP_WAIT1();
        } else {
            CP_WAIT0();
        }
        __syncthreads();

        const float* Ks = (const float*)(dyn + QSZ + (size_t)buf * KSZ);
        const float* Vs = (const float*)(dyn + QSZ + 2 * KSZ + (size_t)buf * KSZ);

        // ---- S = Q KP^T : warp tile 32 rows x 64 keys ----
        float accs[2][8][4];
        #pragma unroll
        for (int i = 0; i < 2; ++i)
            #pragma unroll
            for (int j = 0; j < 8; ++j)
                #pragma unroll
                for (int k = 0; k < 4; ++k) accs[i][j][k] = 0.f;

        #pragma unroll
        for (int kk = 0; kk < 8; ++kk) {
            #pragma unroll
            for (int ni = 0; ni < 8; ++ni) {
                float2 fb = *(const float2*)(Ks + (ni * 8 + g) * ALD + kk * 8 + 2 * tg);
                uint32_t b0 = __float_as_uint(fb.x);
                uint32_t b1 = __float_as_uint(fb.y);
                mma8(accs[0][ni], qf[0][kk], b0, b1);
                mma8(accs[1][ni], qf[1][kk], b0, b1);
            }
        }

        // ---- register softmax (rows g / g+8 per mi; shfl over tg group) ----
        float rs0[2], rs1[2];
        #pragma unroll
        for (int mi = 0; mi < 2; ++mi) {
            float a0 = -1e30f, a1 = -1e30f;
            #pragma unroll
            for (int ni = 0; ni < 8; ++ni) {
                a0 = fmaxf(a0, fmaxf(accs[mi][ni][0], accs[mi][ni][1]));
                a1 = fmaxf(a1, fmaxf(accs[mi][ni][2], accs[mi][ni][3]));
            }
            a0 = fmaxf(a0, __shfl_xor_sync(0xffffffffu, a0, 1));
            a0 = fmaxf(a0, __shfl_xor_sync(0xffffffffu, a0, 2));
            a1 = fmaxf(a1, __shfl_xor_sync(0xffffffffu, a1, 1));
            a1 = fmaxf(a1, __shfl_xor_sync(0xffffffffu, a1, 2));
            float mn0 = fmaxf(mr0[mi], a0 * 0.125f);
            float mn1 = fmaxf(mr1[mi], a1 * 0.125f);
            rs0[mi] = __expf(mr0[mi] - mn0);
            rs1[mi] = __expf(mr1[mi] - mn1);
            float ls0 = 0.f, ls1 = 0.f;
            #pragma unroll
            for (int ni = 0; ni < 8; ++ni) {
                float p0 = __expf(accs[mi][ni][0] * 0.125f - mn0);
                float p1 = __expf(accs[mi][ni][1] * 0.125f - mn0);
                float p2 = __expf(accs[mi][ni][2] * 0.125f - mn1);
                float p3 = __expf(accs[mi][ni][3] * 0.125f - mn1);
                ls0 += p0 + p1; ls1 += p2 + p3;
                accs[mi][ni][0] = p0; accs[mi][ni][1] = p1;
                accs[mi][ni][2] = p2; accs[mi][ni][3] = p3;
            }
            ls0 += __shfl_xor_sync(0xffffffffu, ls0, 1);
            ls0 += __shfl_xor_sync(0xffffffffu, ls0, 2);
            ls1 += __shfl_xor_sync(0xffffffffu, ls1, 1);
            ls1 += __shfl_xor_sync(0xffffffffu, ls1, 2);
            lr0[mi] = lr0[mi] * rs0[mi] + ls0;
            lr1[mi] = lr1[mi] * rs1[mi] + ls1;
            mr0[mi] = mn0; mr1[mi] = mn1;
        }

        // rescale O accumulators
        #pragma unroll
        for (int mi = 0; mi < 2; ++mi)
            #pragma unroll
            for (int ni = 0; ni < 8; ++ni) {
                acco[mi][ni][0] *= rs0[mi];
                acco[mi][ni][1] *= rs0[mi];
                acco[mi][ni][2] *= rs1[mi];
                acco[mi][ni][3] *= rs1[mi];
            }

        // ---- P (C-frag) -> A-frag via shuffles, then O += P V ----
        const int srcA = (lane & ~3) | (tg >> 1);
        const int srcB = srcA + 2;
        const bool od = (tg & 1);
        #pragma unroll
        for (int j = 0; j < 8; ++j) {
            uint32_t pa[2][4];
            #pragma unroll
            for (int mi = 0; mi < 2; ++mi) {
                float v0 = accs[mi][j][0], v1 = accs[mi][j][1];
                float v2 = accs[mi][j][2], v3 = accs[mi][j][3];
                float s0a = __shfl_sync(0xffffffffu, v0, srcA);
                float s1a = __shfl_sync(0xffffffffu, v1, srcA);
                float t0a = __shfl_sync(0xffffffffu, v0, srcB);
                float t1a = __shfl_sync(0xffffffffu, v1, srcB);
                float u0a = __shfl_sync(0xffffffffu, v2, srcA);
                float u1a = __shfl_sync(0xffffffffu, v3, srcA);
                float w0a = __shfl_sync(0xffffffffu, v2, srcB);
                float w1a = __shfl_sync(0xffffffffu, v3, srcB);
                pa[mi][0] = tf32b(od ? s1a : s0a);   // (row g,   k=tg)
                pa[mi][1] = tf32b(od ? u1a : u0a);   // (row g+8, k=tg)
                pa[mi][2] = tf32b(od ? t1a : t0a);   // (row g,   k=tg+4)
                pa[mi][3] = tf32b(od ? w1a : w0a);   // (row g+8, k=tg+4)
            }
            #pragma unroll
            for (int ni = 0; ni < 8; ++ni) {
                float2 fb = *(const float2*)(Vs + (ni * 8 + g) * ALD + j * 8 + 2 * tg);
                uint32_t b0 = __float_as_uint(fb.x);
                uint32_t b1 = __float_as_uint(fb.y);
                mma8(acco[0][ni], pa[0], b0, b1);
                mma8(acco[1][ni], pa[1], b0, b1);
            }
        }
        __syncthreads();
    }

    // ---- normalize, write ctx (paired cols for the out GEMM) ----
    const int b_ = bh >> 3, h = bh & 7;
    #pragma unroll
    for (int mi = 0; mi < 2; ++mi) {
        int rA = wm * 32 + mi * 16 + g;
        float iA = 1.f / lr0[mi];
        float iB = 1.f / lr1[mi];
        #pragma unroll
        for (int ni = 0; ni < 8; ++ni) {
            int c0 = ni * 8 + tg * 2, c1 = c0 + 1;
            size_t o0 = ((size_t)(b_ * TT + q0 + rA)) * DD + h * 64;
            size_t o1 = ((size_t)(b_ * TT + q0 + rA + 8)) * DD + h * 64;
            g_C[o0 + perm8(c0)] = tf32r(acco[mi][ni][0] * iA);
            g_C[o0 + perm8(c1)] = tf32r(acco[mi][ni][1] * iA);
            g_C[o1 + perm8(c0)] = tf32r(acco[mi][ni][2] * iB);
            g_C[o1 + perm8(c1)] = tf32r(acco[mi][ni][3] * iB);
        }
    }
}

// ---------------------------------------------------------------------------
// Kernel 3: out = ctx @ Wo^T + bo
// ---------------------------------------------------------------------------
__global__ void __launch_bounds__(256, 2) out_mma(const float* __restrict__ bo,
                                                 float* __restrict__ out)
{
    extern __shared__ char dyn[];
    float acc[2][8][4];
    #pragma unroll
    for (int i = 0; i < 2; ++i)
        #pragma unroll
        for (int j = 0; j < 8; ++j)
            #pragma unroll
            for (int k = 0; k < 4; ++k) acc[i][j][k] = 0.f;

    const int tid = threadIdx.x;
    const int n0 = blockIdx.x * 128;
    const int m0 = blockIdx.y * 128;
    const float* Wo = g_Wc + (size_t)4 * DD * DD;

    gemm_pipe(g_C, Wo, nullptr, nullptr, m0, n0, acc, dyn, tid);

    const int lane = tid & 31, warp = tid >> 5;
    const int wm = warp >> 1, wn = warp & 1;
    const int g = lane >> 2, tg = lane & 3;
    #pragma unroll
    for (int mi = 0; mi < 2; ++mi) {
        #pragma unroll
        for (int ni = 0; ni < 8; ++ni) {
            int r = m0 + wm * 32 + mi * 16 + g;
            int c = n0 + wn * 64 + ni * 8 + tg * 2;
            #pragma unroll
            for (int e = 0; e < 4; ++e) {
                int m = r + ((e >= 2) ? 8 : 0);
                int n = c + (e & 1);
                out[(size_t)m * DD + n] = acc[mi][ni][e] + bo[n];
            }
        }
    }
}

// ---------------------------------------------------------------------------
// Launch
// ---------------------------------------------------------------------------
extern "C" void kernel_launch(void* const* d_in, const int* in_sizes, int n_in,
                              void* d_out, int out_size)
{
    (void)in_sizes; (void)n_in; (void)out_size;
    const float* x   = (const float*)d_in[0];
    const float* pos = (const float*)d_in[1];
    const float* Wq  = (const float*)d_in[2];
    const float* bq  = (const float*)d_in[3];
    const float* Wk  = (const float*)d_in[4];
    const float* bk  = (const float*)d_in[5];
    const float* Wv  = (const float*)d_in[6];
    const float* bv  = (const float*)d_in[7];
    const float* Wp  = (const float*)d_in[8];
    const float* bp  = (const float*)d_in[9];
    const float* Wo  = (const float*)d_in[10];
    const float* bo  = (const float*)d_in[11];
    float* out = (float*)d_out;

    const int n4x = MTOT * DD / 4;
    const int n4w = DD * DD / 4;

    cvt_kernel<<<2048, 256>>>((const float4*)x,   0, n4x);
    cvt_kernel<<<2048, 256>>>((const float4*)pos, 1, n4x);
    cvt_kernel<<<256, 256>>>((const float4*)Wq, 2, n4w);
    cvt_kernel<<<256, 256>>>((const float4*)Wk, 3, n4w);
    cvt_kernel<<<256, 256>>>((const float4*)Wv, 4, n4w);
    cvt_kernel<<<256, 256>>>((const float4*)Wp, 5, n4w);
    cvt_kernel<<<256, 256>>>((const float4*)Wo, 6, n4w);

    const int smem_g = 2 * BUFSZ;                 // 81920
    const int smem_a = QSZ + 4 * KSZ;             // 36864 + 73728 = 110592
    cudaFuncSetAttribute(proj_mma, cudaFuncAttributeMaxDynamicSharedMemorySize, smem_g);
    cudaFuncSetAttribute(attn_mma, cudaFuncAttributeMaxDynamicSharedMemorySize, smem_a);
    cudaFuncSetAttribute(out_mma,  cudaFuncAttributeMaxDynamicSharedMemorySize, smem_g);

    proj_mma<<<dim3(4, 128, 3), 256, smem_g>>>(bq, bk, bv, bp);
    attn_mma<<<dim3(16, 64), 128, smem_a>>>();
    out_mma<<<dim3(4, 128), 256, smem_g>>>(bo, out);
}

// round 10
// speedup vs baseline: 3.1358x; 1.9650x over previous
#include <cuda_runtime.h>
#include <cuda_fp16.h>
#include <cstdint>
#include <cstddef>

#define BB   8
#define TT   2048
#define DD   512
#define HH   8
#define DHH  64
#define MTOT (BB*TT)

// Scratch (device globals; no allocation allowed) — all fp16
__device__ __align__(16) __half g_xc[(size_t)MTOT*DD];
__device__ __align__(16) __half g_pc[(size_t)MTOT*DD];
__device__ __align__(16) __half g_Wc[5*DD*DD];            // Wq,Wk,Wv,Wp,Wo
__device__ __align__(16) __half g_Q [BB*HH*TT*DHH];       // [bh][t][dh] (pre-scaled by 1/8)
__device__ __align__(16) __half g_KP[BB*HH*TT*DHH];       // [bh][t][dh]
__device__ __align__(16) __half g_V [BB*HH*TT*DHH];       // [bh][t][dh]
__device__ __align__(16) __half g_C [(size_t)MTOT*DD];    // ctx

// ---------------------------------------------------------------------------
// Helpers
// ---------------------------------------------------------------------------
__device__ __forceinline__ uint32_t pack_h2(float a, float b) {
    __half2 h = __floats2half2_rn(a, b);
    return *reinterpret_cast<uint32_t*>(&h);
}
__device__ __forceinline__ void mma16(float* d, const uint32_t* a, uint32_t b0, uint32_t b1) {
    asm volatile(
        "mma.sync.aligned.m16n8k16.row.col.f32.f16.f16.f32 "
        "{%0,%1,%2,%3}, {%4,%5,%6,%7}, {%8,%9}, {%0,%1,%2,%3};\n"
        : "+f"(d[0]), "+f"(d[1]), "+f"(d[2]), "+f"(d[3])
        : "r"(a[0]), "r"(a[1]), "r"(a[2]), "r"(a[3]), "r"(b0), "r"(b1));
}
__device__ __forceinline__ void ldsm4(uint32_t& r0, uint32_t& r1, uint32_t& r2, uint32_t& r3, uint32_t a) {
    asm volatile("ldmatrix.sync.aligned.m8n8.x4.shared.b16 {%0,%1,%2,%3}, [%4];"
        : "=r"(r0), "=r"(r1), "=r"(r2), "=r"(r3) : "r"(a));
}
__device__ __forceinline__ void ldsm4t(uint32_t& r0, uint32_t& r1, uint32_t& r2, uint32_t& r3, uint32_t a) {
    asm volatile("ldmatrix.sync.aligned.m8n8.x4.trans.shared.b16 {%0,%1,%2,%3}, [%4];"
        : "=r"(r0), "=r"(r1), "=r"(r2), "=r"(r3) : "r"(a));
}
__device__ __forceinline__ uint32_t s2u(const void* p) {
    uint32_t a;
    asm("{ .reg .u64 t; cvta.to.shared.u64 t, %1; cvt.u32.u64 %0, t; }" : "=r"(a) : "l"(p));
    return a;
}
#define CP16(d, s)   asm volatile("cp.async.cg.shared.global [%0], [%1], 16;" :: "r"(d), "l"(s))
#define CP_COMMIT()  asm volatile("cp.async.commit_group;" ::: "memory")
#define CP_WAIT0()   asm volatile("cp.async.wait_group 0;" ::: "memory")
#define CP_WAIT1()   asm volatile("cp.async.wait_group 1;" ::: "memory")

// ---------------------------------------------------------------------------
// Kernel 0a/0b: f32 -> f16 conversion
// ---------------------------------------------------------------------------
__global__ void __launch_bounds__(256) cvt_xp(const float4* __restrict__ x,
                                              const float4* __restrict__ p, int n4)
{
    int i = blockIdx.x * blockDim.x + threadIdx.x;
    int st = gridDim.x * blockDim.x;
    for (; i < 2 * n4; i += st) {
        bool first = i < n4;
        int j = first ? i : i - n4;
        float4 v = (first ? x : p)[j];
        uint2 o = make_uint2(pack_h2(v.x, v.y), pack_h2(v.z, v.w));
        ((uint2*)(first ? g_xc : g_pc))[j] = o;
    }
}
__global__ void __launch_bounds__(256) cvt_w(const float4* __restrict__ w0,
                                             const float4* __restrict__ w1,
                                             const float4* __restrict__ w2,
                                             const float4* __restrict__ w3,
                                             const float4* __restrict__ w4, int n4)
{
    int i = blockIdx.x * blockDim.x + threadIdx.x;
    int st = gridDim.x * blockDim.x;
    for (; i < 5 * n4; i += st) {
        int w = i / n4, j = i - w * n4;
        const float4* s = (w == 0) ? w0 : (w == 1) ? w1 : (w == 2) ? w2 : (w == 3) ? w3 : w4;
        float4 v = s[j];
        uint2 o = make_uint2(pack_h2(v.x, v.y), pack_h2(v.z, v.w));
        ((uint2*)g_Wc)[(size_t)w * n4 + j] = o;
    }
}

// ---------------------------------------------------------------------------
// fp16 tiled GEMM: block 128x128, BK=64 halfs, cp.async double buffer.
// 256 thr = 8 warps (4m x 2n); warp tile 32x64. Row stride 144B (72 halfs).
// ---------------------------------------------------------------------------
#define ROWB 144
#define TSZ  (128*ROWB)          // 18432 B per matrix
#define GBUF (2*TSZ)             // 36864 B per buffer (A+B)

__device__ __forceinline__ void gstage(const __half* __restrict__ A, const __half* __restrict__ W,
                                       int m0, int n0, int kc, uint32_t sbase, int tid)
{
    #pragma unroll
    for (int j = 0; j < 4; ++j) {
        int c = tid + j * 256;               // 0..1023: 128 rows x 8 chunks
        int row = c >> 3, ch = c & 7;
        uint32_t d = sbase + (uint32_t)row * ROWB + (uint32_t)ch * 16;
        CP16(d,       (const void*)(A + (size_t)(m0 + row) * DD + kc + ch * 8));
        CP16(d + TSZ, (const void*)(W + (size_t)(n0 + row) * DD + kc + ch * 8));
    }
}

__device__ __forceinline__ void gcompute(uint32_t Ab, uint32_t Bb, float acc[2][8][4],
                                         int wm, int wn, int lane)
{
    const int arow = (lane & 7) + ((lane >> 3) & 1) * 8;
    const int akof = (lane >> 4) * 8;
    const int brow = (lane & 7) + (lane >> 4) * 8;
    const int bkof = ((lane >> 3) & 1) * 8;
    #pragma unroll
    for (int kk = 0; kk < 4; ++kk) {
        uint32_t af[2][4];
        #pragma unroll
        for (int mi = 0; mi < 2; ++mi)
            ldsm4(af[mi][0], af[mi][1], af[mi][2], af[mi][3],
                  Ab + (uint32_t)(wm * 32 + mi * 16 + arow) * ROWB + (uint32_t)(kk * 16 + akof) * 2);
        #pragma unroll
        for (int nip = 0; nip < 4; ++nip) {
            uint32_t b0, b1, b2, b3;
            ldsm4(b0, b1, b2, b3,
                  Bb + (uint32_t)(wn * 64 + nip * 16 + brow) * ROWB + (uint32_t)(kk * 16 + bkof) * 2);
            mma16(acc[0][2 * nip],     af[0], b0, b1);
            mma16(acc[1][2 * nip],     af[1], b0, b1);
            mma16(acc[0][2 * nip + 1], af[0], b2, b3);
            mma16(acc[1][2 * nip + 1], af[1], b2, b3);
        }
    }
}

__device__ void gemm_pipe(const __half* A0, const __half* W0,
                          const __half* A1, const __half* W1,
                          int m0, int n0, float acc[2][8][4],
                          char* dyn, int tid)
{
    const uint32_t s0 = s2u(dyn);
    const int T = A1 ? 16 : 8;
    const int lane = tid & 31, warp = tid >> 5;
    const int wm = warp >> 1, wn = warp & 1;

    gstage(A0, W0, m0, n0, 0, s0, tid);
    CP_COMMIT();
    for (int it = 0; it < T; ++it) {
        if (it + 1 < T) {
            int it2 = it + 1;
            const __half* A = (it2 < 8) ? A0 : A1;
            const __half* W = (it2 < 8) ? W0 : W1;
            gstage(A, W, m0, n0, (it2 & 7) * 64, s0 + (uint32_t)(it2 & 1) * GBUF, tid);
            CP_COMMIT();
            CP_WAIT1();
        } else {
            CP_WAIT0();
        }
        __syncthreads();
        uint32_t base = s0 + (uint32_t)(it & 1) * GBUF;
        gcompute(base, base + TSZ, acc, wm, wn, lane);
        __syncthreads();
    }
}

// ---------------------------------------------------------------------------
// Kernel 1: projections. z=0 -> KP (K=1024), z=1 -> Q (x 1/8), z=2 -> V.
// ---------------------------------------------------------------------------
__global__ void __launch_bounds__(256, 2) proj_mma(
    const float* __restrict__ bq, const float* __restrict__ bk,
    const float* __restrict__ bv, const float* __restrict__ bp)
{
    extern __shared__ char dyn[];
    float acc[2][8][4];
    #pragma unroll
    for (int i = 0; i < 2; ++i)
        #pragma unroll
        for (int j = 0; j < 8; ++j)
            #pragma unroll
            for (int k = 0; k < 4; ++k) acc[i][j][k] = 0.f;

    const int tid = threadIdx.x;
    const int n0 = blockIdx.x * 128;
    const int m0 = blockIdx.y * 128;
    const int z  = blockIdx.z;

    const __half* Wq = g_Wc;
    const __half* Wk = g_Wc + (size_t)1 * DD * DD;
    const __half* Wv = g_Wc + (size_t)2 * DD * DD;
    const __half* Wp = g_Wc + (size_t)3 * DD * DD;

    const float *b1, *b2 = nullptr;
    __half* dst;
    float scl = 1.f;
    if (z == 0)      { gemm_pipe(g_xc, Wk, g_pc, Wp, m0, n0, acc, dyn, tid); b1 = bk; b2 = bp; dst = g_KP; }
    else if (z == 1) { gemm_pipe(g_xc, Wq, nullptr, nullptr, m0, n0, acc, dyn, tid); b1 = bq; dst = g_Q; scl = 0.125f; }
    else             { gemm_pipe(g_xc, Wv, nullptr, nullptr, m0, n0, acc, dyn, tid); b1 = bv; dst = g_V; }

    const int lane = tid & 31, warp = tid >> 5;
    const int wm = warp >> 1, wn = warp & 1;
    const int g = lane >> 2, tg = lane & 3;
    #pragma unroll
    for (int mi = 0; mi < 2; ++mi) {
        #pragma unroll
        for (int ni = 0; ni < 8; ++ni) {
            int r = m0 + wm * 32 + mi * 16 + g;
            int c = n0 + wn * 64 + ni * 8 + tg * 2;
            int h = c >> 6, d = c & 63;
            float v0 = (acc[mi][ni][0] + b1[c]     + (b2 ? b2[c]     : 0.f)) * scl;
            float v1 = (acc[mi][ni][1] + b1[c + 1] + (b2 ? b2[c + 1] : 0.f)) * scl;
            float v2 = (acc[mi][ni][2] + b1[c]     + (b2 ? b2[c]     : 0.f)) * scl;
            float v3 = (acc[mi][ni][3] + b1[c + 1] + (b2 ? b2[c + 1] : 0.f)) * scl;
            int b_ = r >> 11, t0 = r & 2047;
            size_t i0 = ((size_t)(b_ * HH + h) * TT + t0) * DHH + d;
            size_t i1 = ((size_t)(b_ * HH + h) * TT + t0 + 8) * DHH + d;
            *(uint32_t*)(dst + i0) = pack_h2(v0, v1);
            *(uint32_t*)(dst + i1) = pack_h2(v2, v3);
        }
    }
}

// ---------------------------------------------------------------------------
// Kernel 2: fp16 register-resident flash attention.
// Block = (b,h) x 128 q-rows, 128 thr = 4 warps x 32 rows; 64-key chunks.
// P conversion is direct C-frag -> A-frag (fp16 layout identity).
// ---------------------------------------------------------------------------
#define KROWB 144
#define QSZ (128*KROWB)          // 18432
#define KSZ (64*KROWB)           // 9216

__device__ __forceinline__ void stage_kv(int bh, int kb, uint32_t ks, uint32_t vs, int tid)
{
    const __half* Ksrc = g_KP + ((size_t)bh * TT + kb) * DHH;
    const __half* Vsrc = g_V  + ((size_t)bh * TT + kb) * DHH;
    #pragma unroll
    for (int j = 0; j < 4; ++j) {
        int c = tid + j * 128;               // 0..511: 64 rows x 8 chunks
        int row = c >> 3, ch = c & 7;
        uint32_t off = (uint32_t)row * KROWB + (uint32_t)ch * 16;
        CP16(ks + off, (const void*)(Ksrc + (size_t)row * DHH + ch * 8));
        CP16(vs + off, (const void*)(Vsrc + (size_t)row * DHH + ch * 8));
    }
}

__global__ void __launch_bounds__(128) attn_mma()
{
    extern __shared__ char dyn[];
    const uint32_t s0 = s2u(dyn);

    const int tid  = threadIdx.x;
    const int lane = tid & 31, wm = tid >> 5;     // 4 warps x 32 rows
    const int bh = blockIdx.y;
    const int q0 = blockIdx.x * 128;

    // stage Q + chunk 0
    {
        const __half* Qsrc = g_Q + ((size_t)bh * TT + q0) * DHH;
        #pragma unroll
        for (int j = 0; j < 8; ++j) {
            int c = tid + j * 128;                // 128 rows x 8 chunks
            int row = c >> 3, ch = c & 7;
            CP16(s0 + (uint32_t)row * KROWB + (uint32_t)ch * 16,
                 (const void*)(Qsrc + (size_t)row * DHH + ch * 8));
        }
    }
    stage_kv(bh, 0, s0 + QSZ, s0 + QSZ + 2 * KSZ, tid);
    CP_COMMIT();
    CP_WAIT0();
    __syncthreads();

    const int arow = (lane & 7) + ((lane >> 3) & 1) * 8;
    const int akof = (lane >> 4) * 8;
    const int brow = (lane & 7) + (lane >> 4) * 8;       // ldsm non-trans (K)
    const int bkof = ((lane >> 3) & 1) * 8;
    const int vrow = (lane & 7) + ((lane >> 3) & 1) * 8; // ldsm trans (V): row=key
    const int vcol = (lane >> 4) * 8;                    // col=dh

    // Q fragments -> registers (once)
    uint32_t qf[2][4][4];
    #pragma unroll
    for (int mi = 0; mi < 2; ++mi)
        #pragma unroll
        for (int kk = 0; kk < 4; ++kk)
            ldsm4(qf[mi][kk][0], qf[mi][kk][1], qf[mi][kk][2], qf[mi][kk][3],
                  s0 + (uint32_t)(wm * 32 + mi * 16 + arow) * KROWB + (uint32_t)(kk * 16 + akof) * 2);

    float acco[2][8][4];
    #pragma unroll
    for (int i = 0; i < 2; ++i)
        #pragma unroll
        for (int j = 0; j < 8; ++j)
            #pragma unroll
            for (int k = 0; k < 4; ++k) acco[i][j][k] = 0.f;
    float mr0[2] = {-1e30f, -1e30f}, mr1[2] = {-1e30f, -1e30f};
    float lr0[2] = {0.f, 0.f},       lr1[2] = {0.f, 0.f};

    for (int cb = 0; cb < 32; ++cb) {
        const int buf = cb & 1;
        if (cb + 1 < 32) {
            stage_kv(bh, (cb + 1) * 64,
                     s0 + QSZ + (uint32_t)(buf ^ 1) * KSZ,
                     s0 + QSZ + 2 * KSZ + (uint32_t)(buf ^ 1) * KSZ, tid);
            CP_COMMIT();
            CP_WAIT1();
        } else {
            CP_WAIT0();
        }
        __syncthreads();

        const uint32_t Ks = s0 + QSZ + (uint32_t)buf * KSZ;
        const uint32_t Vs = s0 + QSZ + 2 * KSZ + (uint32_t)buf * KSZ;

        // ---- S = Q KP^T (scores pre-scaled via Q) ----
        float accs[2][8][4];
        #pragma unroll
        for (int i = 0; i < 2; ++i)
            #pragma unroll
            for (int j = 0; j < 8; ++j)
                #pragma unroll
                for (int k = 0; k < 4; ++k) accs[i][j][k] = 0.f;

        #pragma unroll
        for (int kk = 0; kk < 4; ++kk) {
            #pragma unroll
            for (int nip = 0; nip < 4; ++nip) {
                uint32_t b0, b1, b2, b3;
                ldsm4(b0, b1, b2, b3,
                      Ks + (uint32_t)(nip * 16 + brow) * KROWB + (uint32_t)(kk * 16 + bkof) * 2);
                mma16(accs[0][2 * nip],     qf[0][kk], b0, b1);
                mma16(accs[1][2 * nip],     qf[1][kk], b0, b1);
                mma16(accs[0][2 * nip + 1], qf[0][kk], b2, b3);
                mma16(accs[1][2 * nip + 1], qf[1][kk], b2, b3);
            }
        }

        // ---- register online softmax ----
        float rs0[2], rs1[2];
        #pragma unroll
        for (int mi = 0; mi < 2; ++mi) {
            float a0 = -1e30f, a1 = -1e30f;
            #pragma unroll
            for (int ni = 0; ni < 8; ++ni) {
                a0 = fmaxf(a0, fmaxf(accs[mi][ni][0], accs[mi][ni][1]));
                a1 = fmaxf(a1, fmaxf(accs[mi][ni][2], accs[mi][ni][3]));
            }
            a0 = fmaxf(a0, __shfl_xor_sync(0xffffffffu, a0, 1));
            a0 = fmaxf(a0, __shfl_xor_sync(0xffffffffu, a0, 2));
            a1 = fmaxf(a1, __shfl_xor_sync(0xffffffffu, a1, 1));
            a1 = fmaxf(a1, __shfl_xor_sync(0xffffffffu, a1, 2));
            float mn0 = fmaxf(mr0[mi], a0);
            float mn1 = fmaxf(mr1[mi], a1);
            rs0[mi] = __expf(mr0[mi] - mn0);
            rs1[mi] = __expf(mr1[mi] - mn1);
            float ls0 = 0.f, ls1 = 0.f;
            #pragma unroll
            for (int ni = 0; ni < 8; ++ni) {
                float p0 = __expf(accs[mi][ni][0] - mn0);
                float p1 = __expf(accs[mi][ni][1] - mn0);
                float p2 = __expf(accs[mi][ni][2] - mn1);
                float p3 = __expf(accs[mi][ni][3] - mn1);
                ls0 += p0 + p1; ls1 += p2 + p3;
                accs[mi][ni][0] = p0; accs[mi][ni][1] = p1;
                accs[mi][ni][2] = p2; accs[mi][ni][3] = p3;
            }
            ls0 += __shfl_xor_sync(0xffffffffu, ls0, 1);
            ls0 += __shfl_xor_sync(0xffffffffu, ls0, 2);
            ls1 += __shfl_xor_sync(0xffffffffu, ls1, 1);
            ls1 += __shfl_xor_sync(0xffffffffu, ls1, 2);
            lr0[mi] = lr0[mi] * rs0[mi] + ls0;
            lr1[mi] = lr1[mi] * rs1[mi] + ls1;
            mr0[mi] = mn0; mr1[mi] = mn1;
        }

        // rescale O
        #pragma unroll
        for (int mi = 0; mi < 2; ++mi)
            #pragma unroll
            for (int ni = 0; ni < 8; ++ni) {
                acco[mi][ni][0] *= rs0[mi];
                acco[mi][ni][1] *= rs0[mi];
                acco[mi][ni][2] *= rs1[mi];
                acco[mi][ni][3] *= rs1[mi];
            }

        // ---- O += P V  (C-frag -> A-frag is identity in fp16) ----
        #pragma unroll
        for (int j = 0; j < 4; ++j) {          // key chunk of 16
            uint32_t pa[2][4];
            #pragma unroll
            for (int mi = 0; mi < 2; ++mi) {
                pa[mi][0] = pack_h2(accs[mi][2 * j][0],     accs[mi][2 * j][1]);
                pa[mi][1] = pack_h2(accs[mi][2 * j][2],     accs[mi][2 * j][3]);
                pa[mi][2] = pack_h2(accs[mi][2 * j + 1][0], accs[mi][2 * j + 1][1]);
                pa[mi][3] = pack_h2(accs[mi][2 * j + 1][2], accs[mi][2 * j + 1][3]);
            }
            #pragma unroll
            for (int nip = 0; nip < 4; ++nip) {
                uint32_t b0, b1, b2, b3;
                ldsm4t(b0, b1, b2, b3,
                       Vs + (uint32_t)(j * 16 + vrow) * KROWB + (uint32_t)(nip * 16 + vcol) * 2);
                mma16(acco[0][2 * nip],     pa[0], b0, b1);
                mma16(acco[1][2 * nip],     pa[1], b0, b1);
                mma16(acco[0][2 * nip + 1], pa[0], b2, b3);
                mma16(acco[1][2 * nip + 1], pa[1], b2, b3);
            }
        }
        __syncthreads();
    }

    // ---- normalize, write ctx ----
    const int g = lane >> 2, tg = lane & 3;
    const int b_ = bh >> 3, h = bh & 7;
    #pragma unroll
    for (int mi = 0; mi < 2; ++mi) {
        int rA = wm * 32 + mi * 16 + g;
        float iA = 1.f / lr0[mi];
        float iB = 1.f / lr1[mi];
        #pragma unroll
        for (int ni = 0; ni < 8; ++ni) {
            int c0 = ni * 8 + tg * 2;
            size_t o0 = ((size_t)(b_ * TT + q0 + rA)) * DD + h * 64 + c0;
            size_t o1 = ((size_t)(b_ * TT + q0 + rA + 8)) * DD + h * 64 + c0;
            *(uint32_t*)(g_C + o0) = pack_h2(acco[mi][ni][0] * iA, acco[mi][ni][1] * iA);
            *(uint32_t*)(g_C + o1) = pack_h2(acco[mi][ni][2] * iB, acco[mi][ni][3] * iB);
        }
    }
}

// ---------------------------------------------------------------------------
// Kernel 3: out = ctx @ Wo^T + bo  (f32 output)
// ---------------------------------------------------------------------------
__global__ void __launch_bounds__(256, 2) out_mma(const float* __restrict__ bo,
                                                 float* __restrict__ out)
{
    extern __shared__ char dyn[];
    float acc[2][8][4];
    #pragma unroll
    for (int i = 0; i < 2; ++i)
        #pragma unroll
        for (int j = 0; j < 8; ++j)
            #pragma unroll
            for (int k = 0; k < 4; ++k) acc[i][j][k] = 0.f;

    const int tid = threadIdx.x;
    const int n0 = blockIdx.x * 128;
    const int m0 = blockIdx.y * 128;
    const __half* Wo = g_Wc + (size_t)4 * DD * DD;

    gemm_pipe(g_C, Wo, nullptr, nullptr, m0, n0, acc, dyn, tid);

    const int lane = tid & 31, warp = tid >> 5;
    const int wm = warp >> 1, wn = warp & 1;
    const int g = lane >> 2, tg = lane & 3;
    #pragma unroll
    for (int mi = 0; mi < 2; ++mi) {
        #pragma unroll
        for (int ni = 0; ni < 8; ++ni) {
            int r = m0 + wm * 32 + mi * 16 + g;
            int c = n0 + wn * 64 + ni * 8 + tg * 2;
            float2 v0 = make_float2(acc[mi][ni][0] + bo[c], acc[mi][ni][1] + bo[c + 1]);
            float2 v1 = make_float2(acc[mi][ni][2] + bo[c], acc[mi][ni][3] + bo[c + 1]);
            *(float2*)(out + (size_t)r * DD + c)       = v0;
            *(float2*)(out + (size_t)(r + 8) * DD + c) = v1;
        }
    }
}

// ---------------------------------------------------------------------------
// Launch
// ---------------------------------------------------------------------------
extern "C" void kernel_launch(void* const* d_in, const int* in_sizes, int n_in,
                              void* d_out, int out_size)
{
    (void)in_sizes; (void)n_in; (void)out_size;
    const float* x   = (const float*)d_in[0];
    const float* pos = (const float*)d_in[1];
    const float* Wq  = (const float*)d_in[2];
    const float* bq  = (const float*)d_in[3];
    const float* Wk  = (const float*)d_in[4];
    const float* bk  = (const float*)d_in[5];
    const float* Wv  = (const float*)d_in[6];
    const float* bv  = (const float*)d_in[7];
    const float* Wp  = (const float*)d_in[8];
    const float* bp  = (const float*)d_in[9];
    const float* Wo  = (const float*)d_in[10];
    const float* bo  = (const float*)d_in[11];
    float* out = (float*)d_out;

    const int n4x = MTOT * DD / 4;
    const int n4w = DD * DD / 4;

    cvt_xp<<<2048, 256>>>((const float4*)x, (const float4*)pos, n4x);
    cvt_w<<<512, 256>>>((const float4*)Wq, (const float4*)Wk, (const float4*)Wv,
                        (const float4*)Wp, (const float4*)Wo, n4w);

    const int smem_g = 2 * GBUF;              // 73728
    const int smem_a = QSZ + 4 * KSZ;         // 18432 + 36864 = 55296
    cudaFuncSetAttribute(proj_mma, cudaFuncAttributeMaxDynamicSharedMemorySize, smem_g);
    cudaFuncSetAttribute(attn_mma, cudaFuncAttributeMaxDynamicSharedMemorySize, smem_a);
    cudaFuncSetAttribute(out_mma,  cudaFuncAttributeMaxDynamicSharedMemorySize, smem_g);

    proj_mma<<<dim3(4, 128, 3), 256, smem_g>>>(bq, bk, bv, bp);
    attn_mma<<<dim3(16, 64), 128, smem_a>>>();
    out_mma<<<dim3(4, 128), 256, smem_g>>>(bo, out);
}

// round 11
// speedup vs baseline: 3.2226x; 1.0277x over previous
#include <cuda_runtime.h>
#include <cuda_fp16.h>
#include <cstdint>
#include <cstddef>

#define BB   8
#define TT   2048
#define DD   512
#define HH   8
#define DHH  64
#define MTOT (BB*TT)

// Scratch (device globals; no allocation allowed) — all fp16
__device__ __align__(16) __half g_xc[(size_t)MTOT*DD];
__device__ __align__(16) __half g_pc[(size_t)MTOT*DD];
__device__ __align__(16) __half g_Wc[5*DD*DD];            // Wq,Wk,Wv,Wp,Wo
__device__ __align__(16) __half g_Q [BB*HH*TT*DHH];       // [bh][t][dh] (pre-scaled by log2e/8)
__device__ __align__(16) __half g_KP[BB*HH*TT*DHH];       // [bh][t][dh]
__device__ __align__(16) __half g_V [BB*HH*TT*DHH];       // [bh][t][dh]
__device__ __align__(16) __half g_C [(size_t)MTOT*DD];    // ctx

// ---------------------------------------------------------------------------
// Helpers
// ---------------------------------------------------------------------------
__device__ __forceinline__ uint32_t pack_h2(float a, float b) {
    __half2 h = __floats2half2_rn(a, b);
    return *reinterpret_cast<uint32_t*>(&h);
}
__device__ __forceinline__ void mma16(float* d, const uint32_t* a, uint32_t b0, uint32_t b1) {
    asm volatile(
        "mma.sync.aligned.m16n8k16.row.col.f32.f16.f16.f32 "
        "{%0,%1,%2,%3}, {%4,%5,%6,%7}, {%8,%9}, {%0,%1,%2,%3};\n"
        : "+f"(d[0]), "+f"(d[1]), "+f"(d[2]), "+f"(d[3])
        : "r"(a[0]), "r"(a[1]), "r"(a[2]), "r"(a[3]), "r"(b0), "r"(b1));
}
__device__ __forceinline__ void ldsm4(uint32_t& r0, uint32_t& r1, uint32_t& r2, uint32_t& r3, uint32_t a) {
    asm volatile("ldmatrix.sync.aligned.m8n8.x4.shared.b16 {%0,%1,%2,%3}, [%4];"
        : "=r"(r0), "=r"(r1), "=r"(r2), "=r"(r3) : "r"(a));
}
__device__ __forceinline__ void ldsm4t(uint32_t& r0, uint32_t& r1, uint32_t& r2, uint32_t& r3, uint32_t a) {
    asm volatile("ldmatrix.sync.aligned.m8n8.x4.trans.shared.b16 {%0,%1,%2,%3}, [%4];"
        : "=r"(r0), "=r"(r1), "=r"(r2), "=r"(r3) : "r"(a));
}
__device__ __forceinline__ uint32_t s2u(const void* p) {
    uint32_t a;
    asm("{ .reg .u64 t; cvta.to.shared.u64 t, %1; cvt.u32.u64 %0, t; }" : "=r"(a) : "l"(p));
    return a;
}
// raw exp2 (single MUFU.EX2, no argument scaling)
__device__ __forceinline__ float ex2(float x) {
    float r; asm("ex2.approx.ftz.f32 %0, %1;" : "=f"(r) : "f"(x));
    return r;
}
#define CP16(d, s)   asm volatile("cp.async.cg.shared.global [%0], [%1], 16;" :: "r"(d), "l"(s))
#define CP_COMMIT()  asm volatile("cp.async.commit_group;" ::: "memory")
#define CP_WAIT0()   asm volatile("cp.async.wait_group 0;" ::: "memory")
#define CP_WAIT1()   asm volatile("cp.async.wait_group 1;" ::: "memory")

// ---------------------------------------------------------------------------
// Kernel 0a/0b: f32 -> f16 conversion
// ---------------------------------------------------------------------------
__global__ void __launch_bounds__(256) cvt_xp(const float4* __restrict__ x,
                                              const float4* __restrict__ p, int n4)
{
    int i = blockIdx.x * blockDim.x + threadIdx.x;
    int st = gridDim.x * blockDim.x;
    for (; i < 2 * n4; i += st) {
        bool first = i < n4;
        int j = first ? i : i - n4;
        float4 v = (first ? x : p)[j];
        uint2 o = make_uint2(pack_h2(v.x, v.y), pack_h2(v.z, v.w));
        ((uint2*)(first ? g_xc : g_pc))[j] = o;
    }
}
__global__ void __launch_bounds__(256) cvt_w(const float4* __restrict__ w0,
                                             const float4* __restrict__ w1,
                                             const float4* __restrict__ w2,
                                             const float4* __restrict__ w3,
                                             const float4* __restrict__ w4, int n4)
{
    int i = blockIdx.x * blockDim.x + threadIdx.x;
    int st = gridDim.x * blockDim.x;
    for (; i < 5 * n4; i += st) {
        int w = i / n4, j = i - w * n4;
        const float4* s = (w == 0) ? w0 : (w == 1) ? w1 : (w == 2) ? w2 : (w == 3) ? w3 : w4;
        float4 v = s[j];
        uint2 o = make_uint2(pack_h2(v.x, v.y), pack_h2(v.z, v.w));
        ((uint2*)g_Wc)[(size_t)w * n4 + j] = o;
    }
}

// ---------------------------------------------------------------------------
// fp16 tiled GEMM: block 128x128, BK=64 halfs, cp.async double buffer.
// 256 thr = 8 warps (4m x 2n); warp tile 32x64. Row stride 144B (72 halfs).
// ---------------------------------------------------------------------------
#define ROWB 144
#define TSZ  (128*ROWB)          // 18432 B per matrix
#define GBUF (2*TSZ)             // 36864 B per buffer (A+B)

__device__ __forceinline__ void gstage(const __half* __restrict__ A, const __half* __restrict__ W,
                                       int m0, int n0, int kc, uint32_t sbase, int tid)
{
    #pragma unroll
    for (int j = 0; j < 4; ++j) {
        int c = tid + j * 256;               // 0..1023: 128 rows x 8 chunks
        int row = c >> 3, ch = c & 7;
        uint32_t d = sbase + (uint32_t)row * ROWB + (uint32_t)ch * 16;
        CP16(d,       (const void*)(A + (size_t)(m0 + row) * DD + kc + ch * 8));
        CP16(d + TSZ, (const void*)(W + (size_t)(n0 + row) * DD + kc + ch * 8));
    }
}

__device__ __forceinline__ void gcompute(uint32_t Ab, uint32_t Bb, float acc[2][8][4],
                                         uint32_t aoff, uint32_t boff)
{
    // Ab/Bb already include the lane-dependent offsets (aoff/boff baked in by caller)
    #pragma unroll
    for (int kk = 0; kk < 4; ++kk) {
        uint32_t af[2][4];
        #pragma unroll
        for (int mi = 0; mi < 2; ++mi)
            ldsm4(af[mi][0], af[mi][1], af[mi][2], af[mi][3],
                  Ab + (uint32_t)(mi * 16) * ROWB + (uint32_t)(kk * 32));
        #pragma unroll
        for (int nip = 0; nip < 4; ++nip) {
            uint32_t b0, b1, b2, b3;
            ldsm4(b0, b1, b2, b3,
                  Bb + (uint32_t)(nip * 16) * ROWB + (uint32_t)(kk * 32));
            mma16(acc[0][2 * nip],     af[0], b0, b1);
            mma16(acc[1][2 * nip],     af[1], b0, b1);
            mma16(acc[0][2 * nip + 1], af[0], b2, b3);
            mma16(acc[1][2 * nip + 1], af[1], b2, b3);
        }
    }
    (void)aoff; (void)boff;
}

__device__ void gemm_pipe(const __half* A0, const __half* W0,
                          const __half* A1, const __half* W1,
                          int m0, int n0, float acc[2][8][4],
                          char* dyn, int tid)
{
    const uint32_t s0 = s2u(dyn);
    const int T = A1 ? 16 : 8;
    const int lane = tid & 31, warp = tid >> 5;
    const int wm = warp >> 1, wn = warp & 1;

    // lane-dependent ldsm offsets (hoisted)
    const uint32_t aoff = (uint32_t)(wm * 32 + (lane & 7) + ((lane >> 3) & 1) * 8) * ROWB
                        + (uint32_t)((lane >> 4) * 8) * 2;
    const uint32_t boff = (uint32_t)(wn * 64 + (lane & 7) + (lane >> 4) * 8) * ROWB
                        + (uint32_t)(((lane >> 3) & 1) * 8) * 2;

    gstage(A0, W0, m0, n0, 0, s0, tid);
    CP_COMMIT();
    for (int it = 0; it < T; ++it) {
        if (it + 1 < T) {
            int it2 = it + 1;
            const __half* A = (it2 < 8) ? A0 : A1;
            const __half* W = (it2 < 8) ? W0 : W1;
            gstage(A, W, m0, n0, (it2 & 7) * 64, s0 + (uint32_t)(it2 & 1) * GBUF, tid);
            CP_COMMIT();
            CP_WAIT1();
        } else {
            CP_WAIT0();
        }
        __syncthreads();
        uint32_t base = s0 + (uint32_t)(it & 1) * GBUF;
        gcompute(base + aoff, base + TSZ + boff, acc, 0, 0);
        __syncthreads();
    }
}

// ---------------------------------------------------------------------------
// Kernel 1: projections. z=0 -> KP (K=1024), z=1 -> Q (x log2e/8), z=2 -> V.
// ---------------------------------------------------------------------------
__global__ void __launch_bounds__(256, 2) proj_mma(
    const float* __restrict__ bq, const float* __restrict__ bk,
    const float* __restrict__ bv, const float* __restrict__ bp)
{
    extern __shared__ char dyn[];
    float acc[2][8][4];
    #pragma unroll
    for (int i = 0; i < 2; ++i)
        #pragma unroll
        for (int j = 0; j < 8; ++j)
            #pragma unroll
            for (int k = 0; k < 4; ++k) acc[i][j][k] = 0.f;

    const int tid = threadIdx.x;
    const int n0 = blockIdx.x * 128;
    const int m0 = blockIdx.y * 128;
    const int z  = blockIdx.z;

    const __half* Wq = g_Wc;
    const __half* Wk = g_Wc + (size_t)1 * DD * DD;
    const __half* Wv = g_Wc + (size_t)2 * DD * DD;
    const __half* Wp = g_Wc + (size_t)3 * DD * DD;

    const float *b1, *b2 = nullptr;
    __half* dst;
    float scl = 1.f;
    if (z == 0)      { gemm_pipe(g_xc, Wk, g_pc, Wp, m0, n0, acc, dyn, tid); b1 = bk; b2 = bp; dst = g_KP; }
    else if (z == 1) { gemm_pipe(g_xc, Wq, nullptr, nullptr, m0, n0, acc, dyn, tid); b1 = bq; dst = g_Q;
                       scl = 0.125f * 1.44269504088896f; }   // fold 1/sqrt(dh) * log2(e)
    else             { gemm_pipe(g_xc, Wv, nullptr, nullptr, m0, n0, acc, dyn, tid); b1 = bv; dst = g_V; }

    const int lane = tid & 31, warp = tid >> 5;
    const int wm = warp >> 1, wn = warp & 1;
    const int g = lane >> 2, tg = lane & 3;
    #pragma unroll
    for (int mi = 0; mi < 2; ++mi) {
        #pragma unroll
        for (int ni = 0; ni < 8; ++ni) {
            int r = m0 + wm * 32 + mi * 16 + g;
            int c = n0 + wn * 64 + ni * 8 + tg * 2;
            int h = c >> 6, d = c & 63;
            float v0 = (acc[mi][ni][0] + b1[c]     + (b2 ? b2[c]     : 0.f)) * scl;
            float v1 = (acc[mi][ni][1] + b1[c + 1] + (b2 ? b2[c + 1] : 0.f)) * scl;
            float v2 = (acc[mi][ni][2] + b1[c]     + (b2 ? b2[c]     : 0.f)) * scl;
            float v3 = (acc[mi][ni][3] + b1[c + 1] + (b2 ? b2[c + 1] : 0.f)) * scl;
            int b_ = r >> 11, t0 = r & 2047;
            size_t i0 = ((size_t)(b_ * HH + h) * TT + t0) * DHH + d;
            size_t i1 = ((size_t)(b_ * HH + h) * TT + t0 + 8) * DHH + d;
            *(uint32_t*)(dst + i0) = pack_h2(v0, v1);
            *(uint32_t*)(dst + i1) = pack_h2(v2, v3);
        }
    }
}

// ---------------------------------------------------------------------------
// Kernel 2: fp16 register-resident flash attention (exp2-domain softmax).
// Block = (b,h) x 128 q-rows, 128 thr = 4 warps x 32 rows; 64-key chunks.
// ---------------------------------------------------------------------------
#define KROWB 144
#define QSZ (128*KROWB)          // 18432
#define KSZ (64*KROWB)           // 9216

__device__ __forceinline__ void stage_kv(int bh, int kb, uint32_t ks, uint32_t vs, int tid)
{
    const __half* Ksrc = g_KP + ((size_t)bh * TT + kb) * DHH;
    const __half* Vsrc = g_V  + ((size_t)bh * TT + kb) * DHH;
    #pragma unroll
    for (int j = 0; j < 4; ++j) {
        int c = tid + j * 128;               // 0..511: 64 rows x 8 chunks
        int row = c >> 3, ch = c & 7;
        uint32_t off = (uint32_t)row * KROWB + (uint32_t)ch * 16;
        CP16(ks + off, (const void*)(Ksrc + (size_t)row * DHH + ch * 8));
        CP16(vs + off, (const void*)(Vsrc + (size_t)row * DHH + ch * 8));
    }
}

__global__ void __launch_bounds__(128) attn_mma()
{
    extern __shared__ char dyn[];
    const uint32_t s0 = s2u(dyn);

    const int tid  = threadIdx.x;
    const int lane = tid & 31, wm = tid >> 5;     // 4 warps x 32 rows
    const int bh = blockIdx.y;
    const int q0 = blockIdx.x * 128;

    // stage Q + chunk 0
    {
        const __half* Qsrc = g_Q + ((size_t)bh * TT + q0) * DHH;
        #pragma unroll
        for (int j = 0; j < 8; ++j) {
            int c = tid + j * 128;                // 128 rows x 8 chunks
            int row = c >> 3, ch = c & 7;
            CP16(s0 + (uint32_t)row * KROWB + (uint32_t)ch * 16,
                 (const void*)(Qsrc + (size_t)row * DHH + ch * 8));
        }
    }
    stage_kv(bh, 0, s0 + QSZ, s0 + QSZ + 2 * KSZ, tid);
    CP_COMMIT();
    CP_WAIT0();
    __syncthreads();

    // hoisted lane-dependent ldsm offsets
    const uint32_t aoff = (uint32_t)((lane & 7) + ((lane >> 3) & 1) * 8) * KROWB
                        + (uint32_t)((lane >> 4) * 8) * 2;
    const uint32_t koff = (uint32_t)((lane & 7) + (lane >> 4) * 8) * KROWB
                        + (uint32_t)(((lane >> 3) & 1) * 8) * 2;
    const uint32_t voff = (uint32_t)((lane & 7) + ((lane >> 3) & 1) * 8) * KROWB
                        + (uint32_t)((lane >> 4) * 8) * 2;

    // per-buffer K/V ldsm bases (hoisted)
    const uint32_t kb[2] = { s0 + QSZ + koff,           s0 + QSZ + KSZ + koff };
    const uint32_t vb[2] = { s0 + QSZ + 2 * KSZ + voff, s0 + QSZ + 3 * KSZ + voff };

    // Q fragments -> registers (once)
    uint32_t qf[2][4][4];
    #pragma unroll
    for (int mi = 0; mi < 2; ++mi)
        #pragma unroll
        for (int kk = 0; kk < 4; ++kk)
            ldsm4(qf[mi][kk][0], qf[mi][kk][1], qf[mi][kk][2], qf[mi][kk][3],
                  s0 + aoff + (uint32_t)(wm * 32 + mi * 16) * KROWB + (uint32_t)(kk * 32));

    float acco[2][8][4];
    #pragma unroll
    for (int i = 0; i < 2; ++i)
        #pragma unroll
        for (int j = 0; j < 8; ++j)
            #pragma unroll
            for (int k = 0; k < 4; ++k) acco[i][j][k] = 0.f;
    float mr0[2] = {-1e30f, -1e30f}, mr1[2] = {-1e30f, -1e30f};
    float lr0[2] = {0.f, 0.f},       lr1[2] = {0.f, 0.f};

    for (int cb = 0; cb < 32; ++cb) {
        const int buf = cb & 1;
        if (cb + 1 < 32) {
            stage_kv(bh, (cb + 1) * 64,
                     s0 + QSZ + (uint32_t)(buf ^ 1) * KSZ,
                     s0 + QSZ + 2 * KSZ + (uint32_t)(buf ^ 1) * KSZ, tid);
            CP_COMMIT();
            CP_WAIT1();
        } else {
            CP_WAIT0();
        }
        __syncthreads();

        const uint32_t Ksb = kb[buf];
        const uint32_t Vsb = vb[buf];

        // ---- S = Q KP^T (scores in log2 units via pre-scaled Q) ----
        float accs[2][8][4];
        #pragma unroll
        for (int i = 0; i < 2; ++i)
            #pragma unroll
            for (int j = 0; j < 8; ++j)
                #pragma unroll
                for (int k = 0; k < 4; ++k) accs[i][j][k] = 0.f;

        #pragma unroll
        for (int kk = 0; kk < 4; ++kk) {
            #pragma unroll
            for (int nip = 0; nip < 4; ++nip) {
                uint32_t b0, b1, b2, b3;
                ldsm4(b0, b1, b2, b3,
                      Ksb + (uint32_t)(nip * 16) * KROWB + (uint32_t)(kk * 32));
                mma16(accs[0][2 * nip],     qf[0][kk], b0, b1);
                mma16(accs[1][2 * nip],     qf[1][kk], b0, b1);
                mma16(accs[0][2 * nip + 1], qf[0][kk], b2, b3);
                mma16(accs[1][2 * nip + 1], qf[1][kk], b2, b3);
            }
        }

        // ---- register online softmax (exp2 domain) ----
        float rs0[2], rs1[2];
        #pragma unroll
        for (int mi = 0; mi < 2; ++mi) {
            float a0 = -1e30f, a1 = -1e30f;
            #pragma unroll
            for (int ni = 0; ni < 8; ++ni) {
                a0 = fmaxf(a0, fmaxf(accs[mi][ni][0], accs[mi][ni][1]));
                a1 = fmaxf(a1, fmaxf(accs[mi][ni][2], accs[mi][ni][3]));
            }
            a0 = fmaxf(a0, __shfl_xor_sync(0xffffffffu, a0, 1));
            a0 = fmaxf(a0, __shfl_xor_sync(0xffffffffu, a0, 2));
            a1 = fmaxf(a1, __shfl_xor_sync(0xffffffffu, a1, 1));
            a1 = fmaxf(a1, __shfl_xor_sync(0xffffffffu, a1, 2));
            float mn0 = fmaxf(mr0[mi], a0);
            float mn1 = fmaxf(mr1[mi], a1);
            rs0[mi] = ex2(mr0[mi] - mn0);
            rs1[mi] = ex2(mr1[mi] - mn1);
            float ls0 = 0.f, ls1 = 0.f;
            #pragma unroll
            for (int ni = 0; ni < 8; ++ni) {
                float p0 = ex2(accs[mi][ni][0] - mn0);
                float p1 = ex2(accs[mi][ni][1] - mn0);
                float p2 = ex2(accs[mi][ni][2] - mn1);
                float p3 = ex2(accs[mi][ni][3] - mn1);
                ls0 += p0 + p1; ls1 += p2 + p3;
                accs[mi][ni][0] = p0; accs[mi][ni][1] = p1;
                accs[mi][ni][2] = p2; accs[mi][ni][3] = p3;
            }
            ls0 += __shfl_xor_sync(0xffffffffu, ls0, 1);
            ls0 += __shfl_xor_sync(0xffffffffu, ls0, 2);
            ls1 += __shfl_xor_sync(0xffffffffu, ls1, 1);
            ls1 += __shfl_xor_sync(0xffffffffu, ls1, 2);
            lr0[mi] = lr0[mi] * rs0[mi] + ls0;
            lr1[mi] = lr1[mi] * rs1[mi] + ls1;
            mr0[mi] = mn0; mr1[mi] = mn1;
        }

        // rescale O
        #pragma unroll
        for (int mi = 0; mi < 2; ++mi)
            #pragma unroll
            for (int ni = 0; ni < 8; ++ni) {
                acco[mi][ni][0] *= rs0[mi];
                acco[mi][ni][1] *= rs0[mi];
                acco[mi][ni][2] *= rs1[mi];
                acco[mi][ni][3] *= rs1[mi];
            }

        // ---- O += P V  (C-frag -> A-frag is identity in fp16) ----
        #pragma unroll
        for (int j = 0; j < 4; ++j) {          // key chunk of 16
            uint32_t pa[2][4];
            #pragma unroll
            for (int mi = 0; mi < 2; ++mi) {
                pa[mi][0] = pack_h2(accs[mi][2 * j][0],     accs[mi][2 * j][1]);
                pa[mi][1] = pack_h2(accs[mi][2 * j][2],     accs[mi][2 * j][3]);
                pa[mi][2] = pack_h2(accs[mi][2 * j + 1][0], accs[mi][2 * j + 1][1]);
                pa[mi][3] = pack_h2(accs[mi][2 * j + 1][2], accs[mi][2 * j + 1][3]);
            }
            #pragma unroll
            for (int nip = 0; nip < 4; ++nip) {
                uint32_t b0, b1, b2, b3;
                ldsm4t(b0, b1, b2, b3,
                       Vsb + (uint32_t)(j * 16) * KROWB + (uint32_t)(nip * 32));
                mma16(acco[0][2 * nip],     pa[0], b0, b1);
                mma16(acco[1][2 * nip],     pa[1], b0, b1);
                mma16(acco[0][2 * nip + 1], pa[0], b2, b3);
                mma16(acco[1][2 * nip + 1], pa[1], b2, b3);
            }
        }
        __syncthreads();
    }

    // ---- normalize, write ctx ----
    const int g = lane >> 2, tg = lane & 3;
    const int b_ = bh >> 3, h = bh & 7;
    #pragma unroll
    for (int mi = 0; mi < 2; ++mi) {
        int rA = wm * 32 + mi * 16 + g;
        float iA = 1.f / lr0[mi];
        float iB = 1.f / lr1[mi];
        #pragma unroll
        for (int ni = 0; ni < 8; ++ni) {
            int c0 = ni * 8 + tg * 2;
            size_t o0 = ((size_t)(b_ * TT + q0 + rA)) * DD + h * 64 + c0;
            size_t o1 = ((size_t)(b_ * TT + q0 + rA + 8)) * DD + h * 64 + c0;
            *(uint32_t*)(g_C + o0) = pack_h2(acco[mi][ni][0] * iA, acco[mi][ni][1] * iA);
            *(uint32_t*)(g_C + o1) = pack_h2(acco[mi][ni][2] * iB, acco[mi][ni][3] * iB);
        }
    }
}

// ---------------------------------------------------------------------------
// Kernel 3: out = ctx @ Wo^T + bo  (f32 output)
// ---------------------------------------------------------------------------
__global__ void __launch_bounds__(256, 2) out_mma(const float* __restrict__ bo,
                                                 float* __restrict__ out)
{
    extern __shared__ char dyn[];
    float acc[2][8][4];
    #pragma unroll
    for (int i = 0; i < 2; ++i)
        #pragma unroll
        for (int j = 0; j < 8; ++j)
            #pragma unroll
            for (int k = 0; k < 4; ++k) acc[i][j][k] = 0.f;

    const int tid = threadIdx.x;
    const int n0 = blockIdx.x * 128;
    const int m0 = blockIdx.y * 128;
    const __half* Wo = g_Wc + (size_t)4 * DD * DD;

    gemm_pipe(g_C, Wo, nullptr, nullptr, m0, n0, acc, dyn, tid);

    const int lane = tid & 31, warp = tid >> 5;
    const int wm = warp >> 1, wn = warp & 1;
    const int g = lane >> 2, tg = lane & 3;
    #pragma unroll
    for (int mi = 0; mi < 2; ++mi) {
        #pragma unroll
        for (int ni = 0; ni < 8; ++ni) {
            int r = m0 + wm * 32 + mi * 16 + g;
            int c = n0 + wn * 64 + ni * 8 + tg * 2;
            float2 v0 = make_float2(acc[mi][ni][0] + bo[c], acc[mi][ni][1] + bo[c + 1]);
            float2 v1 = make_float2(acc[mi][ni][2] + bo[c], acc[mi][ni][3] + bo[c + 1]);
            *(float2*)(out + (size_t)r * DD + c)       = v0;
            *(float2*)(out + (size_t)(r + 8) * DD + c) = v1;
        }
    }
}

// ---------------------------------------------------------------------------
// Launch
// ---------------------------------------------------------------------------
extern "C" void kernel_launch(void* const* d_in, const int* in_sizes, int n_in,
                              void* d_out, int out_size)
{
    (void)in_sizes; (void)n_in; (void)out_size;
    const float* x   = (const float*)d_in[0];
    const float* pos = (const float*)d_in[1];
    const float* Wq  = (const float*)d_in[2];
    const float* bq  = (const float*)d_in[3];
    const float* Wk  = (const float*)d_in[4];
    const float* bk  = (const float*)d_in[5];
    const float* Wv  = (const float*)d_in[6];
    const float* bv  = (const float*)d_in[7];
    const float* Wp  = (const float*)d_in[8];
    const float* bp  = (const float*)d_in[9];
    const float* Wo  = (const float*)d_in[10];
    const float* bo  = (const float*)d_in[11];
    float* out = (float*)d_out;

    const int n4x = MTOT * DD / 4;
    const int n4w = DD * DD / 4;

    cvt_xp<<<2048, 256>>>((const float4*)x, (const float4*)pos, n4x);
    cvt_w<<<512, 256>>>((const float4*)Wq, (const float4*)Wk, (const float4*)Wv,
                        (const float4*)Wp, (const float4*)Wo, n4w);

    const int smem_g = 2 * GBUF;              // 73728
    const int smem_a = QSZ + 4 * KSZ;         // 18432 + 36864 = 55296
    cudaFuncSetAttribute(proj_mma, cudaFuncAttributeMaxDynamicSharedMemorySize, smem_g);
    cudaFuncSetAttribute(attn_mma, cudaFuncAttributeMaxDynamicSharedMemorySize, smem_a);
    cudaFuncSetAttribute(out_mma,  cudaFuncAttributeMaxDynamicSharedMemorySize, smem_g);

    proj_mma<<<dim3(4, 128, 3), 256, smem_g>>>(bq, bk, bv, bp);
    attn_mma<<<dim3(16, 64), 128, smem_a>>>();
    out_mma<<<dim3(4, 128), 256, smem_g>>>(bo, out);
}